// round 13
// baseline (speedup 1.0000x reference)
#include <cuda_runtime.h>
#include <cuda_bf16.h>
#include <cstdint>
#include <math.h>

// ================= problem constants =================
#define LSEQ 4096
#define EMB 2048
#define KVHEADS 4
#define NSLOTS 32
#define NDIMS 1024
#define NCHUNK 128
#define CLEN 32                          // LSEQ / NCHUNK
#define RHALF 0.70710678118654752f
#define INV_SCALE 0.29730177875068026f   // 1 / 128^0.25
#define EPSF 1e-6f
#define KP 6144                          // K' = 3 * 2048 (hi|lo|hi concat)
#define KPITCH 133                       // bank step 5 (coprime 32): conflict-free cols

// ================= device scratch =================
__device__ float d_kk[LSEQ * 512];
__device__ float d_vv[LSEQ * 512];
__device__ float d_qq[LSEQ * 2048];
__device__ float d_lend[NCHUNK * NDIMS * NSLOTS];
__device__ float d_carryb[NCHUNK * NDIMS * NSLOTS];
__device__ float d_amat[NCHUNK * NSLOTS * NSLOTS];
__device__ __nv_bfloat16 d_a3[(size_t)LSEQ * KP];     // q split, later attn split
__device__ __nv_bfloat16 d_a3k[(size_t)LSEQ * KP];    // k split
__device__ __nv_bfloat16 d_a3v[(size_t)LSEQ * KP];    // v split
__device__ __nv_bfloat16 d_w3[(size_t)5120 * KP];
// d_w3 rows: wk@0 (512), wv@512, wq@1024 (2048), wd@3072 (2048)

// ================= gate recurrence =================
template <int KEY>
__device__ __forceinline__ void merge_shift(float (&s)[NSLOTS]) {
  s[KEY] = RHALF * (s[KEY] + s[KEY - 1]);
#pragma unroll
  for (int j = KEY - 1; j >= 1; --j) s[j] = s[j - 1];
}

__device__ __forceinline__ void gate_step(float (&s)[NSLOTS], int kdiv) {
  switch (kdiv) {
    case 1: merge_shift<4>(s); break;
    case 2: merge_shift<8>(s); break;
    case 3: merge_shift<12>(s); break;
    case 4: merge_shift<16>(s); break;
    case 5: merge_shift<20>(s); break;
    case 6: merge_shift<24>(s); break;
    case 7: merge_shift<28>(s); break;
    default:
#pragma unroll
      for (int j = 31; j >= 1; --j) s[j] = s[j - 1];
      break;
  }
}

__device__ __forceinline__ int key_div4(int t) { return __ffs(~(t & 1023)); }

// warp-reduce a square and deposit per-warp partial (lane 0)
__device__ __forceinline__ void norm_part(float val, float* pout, int j, int lane) {
  float sq = val * val;
#pragma unroll
  for (int o = 16; o; o >>= 1) sq += __shfl_xor_sync(0xffffffffu, sq, o);
  if (lane == 0) pout[j] = sq;
}

// recurrence step + store changed slots + per-warp norm partials for changed slots
template <int KEY>
__device__ __forceinline__ void step_store_norm(
    float (&s)[NSLOTS], const float (&kp)[NSLOTS], float* col, float x,
    float* pout, int lane) {
  if (KEY < 32) {
    s[KEY] = RHALF * (s[KEY] + s[KEY - 1]);
    float val = s[KEY] + kp[KEY];
    col[KEY * KPITCH] = val;
    norm_part(val, pout, KEY, lane);
  }
  constexpr int TOP = (KEY < 32) ? KEY : 32;
#pragma unroll
  for (int j = TOP - 1; j >= 1; --j) {
    s[j] = s[j - 1];
    float val = s[j] + kp[j];
    col[j * KPITCH] = val;
    norm_part(val, pout, j, lane);
  }
  s[0] = x;
  float v0 = x + kp[0];
  col[0] = v0;
  norm_part(v0, pout, 0, lane);
}

// ================= split helpers =================
__device__ __forceinline__ void split_bf16(float x, __nv_bfloat16& h, __nv_bfloat16& l) {
  h = __float2bfloat16_rn(x);
  l = __float2bfloat16_rn(x - __bfloat162float(h));
}

// all three activation splits in one launch: z = 0:q, 1:k, 2:v
__global__ __launch_bounds__(256) void split_act_all(
    const float* __restrict__ q, const float* __restrict__ k,
    const float* __restrict__ v, __nv_bfloat16* __restrict__ dq,
    __nv_bfloat16* __restrict__ dk, __nv_bfloat16* __restrict__ dv) {
  const int K = EMB;
  const float* src = (blockIdx.z == 0) ? q : (blockIdx.z == 1) ? k : v;
  __nv_bfloat16* dst = (blockIdx.z == 0) ? dq : (blockIdx.z == 1) ? dk : dv;
  int idx = blockIdx.x * 256 + threadIdx.x;
  float4 vv = ((const float4*)src)[idx];
  int c = (idx % (K / 4)) * 4;
  int r = idx / (K / 4);
  __nv_bfloat16 h0, l0, h1, l1, h2, l2, h3, l3;
  split_bf16(vv.x, h0, l0); split_bf16(vv.y, h1, l1);
  split_bf16(vv.z, h2, l2); split_bf16(vv.w, h3, l3);
  __nv_bfloat162 hA(h0, h1), hB(h2, h3), lA(l0, l1), lB(l2, l3);
  __nv_bfloat16* base = dst + (size_t)r * KP + c;
  *(__nv_bfloat162*)(base) = hA;            *(__nv_bfloat162*)(base + 2) = hB;
  *(__nv_bfloat162*)(base + K) = lA;        *(__nv_bfloat162*)(base + K + 2) = lB;
  *(__nv_bfloat162*)(base + 2 * K) = hA;    *(__nv_bfloat162*)(base + 2 * K + 2) = hB;
}

// all four weight splits in one launch: z = 0:wk, 1:wv, 2:wq, 3:wd
__global__ __launch_bounds__(256) void split_wt_all(
    const float* __restrict__ wk, const float* __restrict__ wv,
    const float* __restrict__ wq, const float* __restrict__ wd,
    __nv_bfloat16* __restrict__ w3) {
  const int K = EMB;
  const int z = blockIdx.z;
  const int N = (z < 2) ? 512 : 2048;
  if (blockIdx.x * 32 >= N) return;
  const float* src = (z == 0) ? wk : (z == 1) ? wv : (z == 2) ? wq : wd;
  __nv_bfloat16* dst = w3 + ((z == 0) ? 0 : (z == 1) ? (size_t)512 * KP
                            : (z == 2) ? (size_t)1024 * KP : (size_t)3072 * KP);
  __shared__ float tile[32][33];
  int n0 = blockIdx.x * 32, k0 = blockIdx.y * 32;
  int tx = threadIdx.x & 31, ty = threadIdx.x >> 5;
#pragma unroll
  for (int i = 0; i < 4; i++)
    tile[ty + 8 * i][tx] = src[(size_t)(k0 + ty + 8 * i) * N + n0 + tx];
  __syncthreads();
#pragma unroll
  for (int i = 0; i < 4; i++) {
    int n = n0 + ty + 8 * i;
    int kk = k0 + tx;
    float x = tile[tx][ty + 8 * i];
    __nv_bfloat16 h, l;
    split_bf16(x, h, l);
    __nv_bfloat16* base = dst + (size_t)n * KP;
    base[kk] = h; base[K + kk] = h; base[2 * K + kk] = l;
  }
}

// ================= bf16 tensor-core GEMM core =================
#define BKC 64
#define GKT (KP / BKC)                  // 96 k-chunks
#define SPITCH 72
#define OPBYTES (128 * SPITCH * 2)
#define STG_BYTES (2 * OPBYTES)
#define GSMEM (3 * STG_BYTES)

__device__ __forceinline__ void mma16816(float (&c)[4], const unsigned (&a)[4],
                                         unsigned b0, unsigned b1) {
  asm volatile(
      "mma.sync.aligned.m16n8k16.row.col.f32.bf16.bf16.f32 "
      "{%0,%1,%2,%3}, {%4,%5,%6,%7}, {%8,%9}, {%0,%1,%2,%3};"
      : "+f"(c[0]), "+f"(c[1]), "+f"(c[2]), "+f"(c[3])
      : "r"(a[0]), "r"(a[1]), "r"(a[2]), "r"(a[3]), "r"(b0), "r"(b1));
}

#define CP16(dst, src) \
  asm volatile("cp.async.cg.shared.global [%0], [%1], 16;" :: "r"(dst), "l"(src))

__device__ __forceinline__ void gemm_tile(
    const __nv_bfloat16* __restrict__ A, const __nv_bfloat16* __restrict__ Bn,
    float* __restrict__ C, int N, float alpha, const float* __restrict__ bias,
    int crow, int ccol, char* smdyn) {
  const int tid = threadIdx.x;
  const int lane = tid & 31, warp = tid >> 5;
  const int wm = (warp & 1) * 64, wn = (warp >> 1) * 32;
  const int g = lane >> 2, t = lane & 3;

  const unsigned sBase = (unsigned)__cvta_generic_to_shared(smdyn);

  const int lrow = tid >> 3;
  const int lcc = (tid & 7) * 8;
  const __nv_bfloat16* gA = A + (size_t)(crow + lrow) * KP + lcc;
  const __nv_bfloat16* gB = Bn + (size_t)(ccol + lrow) * KP + lcc;
  const unsigned oA = (lrow * SPITCH + lcc) * 2;
  const unsigned oB = OPBYTES + (lrow * SPITCH + lcc) * 2;

  float acc[4][4][4];
#pragma unroll
  for (int i = 0; i < 4; i++)
#pragma unroll
    for (int j = 0; j < 4; j++)
#pragma unroll
      for (int r = 0; r < 4; r++) acc[i][j][r] = 0.f;

  const int a_row = wm + (lane & 15);
  const int a_kof = (lane >> 4) << 3;
  const int b_row = wn + ((lane >> 4) << 3) + (lane & 7);
  const int b_kof = ((lane >> 3) & 1) << 3;

#pragma unroll
  for (int p = 0; p < 2; p++) {
    const unsigned so = sBase + p * STG_BYTES;
    const __nv_bfloat16* pa = gA + (size_t)p * BKC;
    const __nv_bfloat16* pb = gB + (size_t)p * BKC;
#pragma unroll
    for (int i = 0; i < 4; i++) {
      CP16(so + oA + i * 32 * SPITCH * 2, pa + (size_t)(i * 32) * KP);
      CP16(so + oB + i * 32 * SPITCH * 2, pb + (size_t)(i * 32) * KP);
    }
    asm volatile("cp.async.commit_group;");
  }

  int st = 0;
  for (int kt = 0; kt < GKT; kt++) {
    if (kt + 2 < GKT) asm volatile("cp.async.wait_group 1;");
    else              asm volatile("cp.async.wait_group 0;");
    __syncthreads();

    if (kt + 2 < GKT) {
      int ns = st + 2; if (ns >= 3) ns -= 3;
      const unsigned so = sBase + ns * STG_BYTES;
      const __nv_bfloat16* pa = gA + (size_t)(kt + 2) * BKC;
      const __nv_bfloat16* pb = gB + (size_t)(kt + 2) * BKC;
#pragma unroll
      for (int i = 0; i < 4; i++) {
        CP16(so + oA + i * 32 * SPITCH * 2, pa + (size_t)(i * 32) * KP);
        CP16(so + oB + i * 32 * SPITCH * 2, pb + (size_t)(i * 32) * KP);
      }
      asm volatile("cp.async.commit_group;");
    }

    const unsigned sA = sBase + st * STG_BYTES;
    const unsigned sB = sA + OPBYTES;
#pragma unroll
    for (int ks = 0; ks < 4; ks++) {
      const int k0 = ks * 16;
      unsigned a[4][4];
#pragma unroll
      for (int i = 0; i < 4; i++) {
        unsigned addr = sA + (((a_row + i * 16) * SPITCH) + k0 + a_kof) * 2;
        asm volatile(
            "ldmatrix.sync.aligned.m8n8.x4.shared.b16 {%0,%1,%2,%3}, [%4];"
            : "=r"(a[i][0]), "=r"(a[i][1]), "=r"(a[i][2]), "=r"(a[i][3])
            : "r"(addr));
      }
      unsigned b[4][2];
#pragma unroll
      for (int jj = 0; jj < 2; jj++) {
        unsigned addr = sB + (((b_row + jj * 16) * SPITCH) + k0 + b_kof) * 2;
        asm volatile(
            "ldmatrix.sync.aligned.m8n8.x4.shared.b16 {%0,%1,%2,%3}, [%4];"
            : "=r"(b[2 * jj][0]), "=r"(b[2 * jj][1]),
              "=r"(b[2 * jj + 1][0]), "=r"(b[2 * jj + 1][1])
            : "r"(addr));
      }
#pragma unroll
      for (int i = 0; i < 4; i++)
#pragma unroll
        for (int j = 0; j < 4; j++) mma16816(acc[i][j], a[i], b[j][0], b[j][1]);
    }
    if (++st == 3) st = 0;
  }

#pragma unroll
  for (int i = 0; i < 4; i++) {
#pragma unroll
    for (int j = 0; j < 4; j++) {
      int row = crow + wm + i * 16 + g;
      int col = ccol + wn + j * 8 + 2 * t;
      float b0 = bias ? bias[col & 127] : 0.f;
      float b1 = bias ? bias[(col + 1) & 127] : 0.f;
      float2 v0 = make_float2(alpha * acc[i][j][0] + b0, alpha * acc[i][j][1] + b1);
      float2 v1 = make_float2(alpha * acc[i][j][2] + b0, alpha * acc[i][j][3] + b1);
      *(float2*)(C + (size_t)row * N + col) = v0;
      *(float2*)(C + (size_t)(row + 8) * N + col) = v1;
    }
  }
}

// merged q+k+v projection GEMM: 768 CTAs
__global__ __launch_bounds__(256, 2) void gemm_qkv(
    const __nv_bfloat16* __restrict__ a3q, const __nv_bfloat16* __restrict__ a3k,
    const __nv_bfloat16* __restrict__ a3v, const __nv_bfloat16* __restrict__ w3,
    float* __restrict__ qq, float* __restrict__ kk, float* __restrict__ vv,
    const float* __restrict__ query_pos) {
  extern __shared__ __align__(128) char smdyn[];
  const int bid = blockIdx.x;
  if (bid < 512) {
    int ccol = (bid & 15) * 128, crow = (bid >> 4) * 128;
    gemm_tile(a3q, w3 + (size_t)1024 * KP, qq, 2048, INV_SCALE, query_pos,
              crow, ccol, smdyn);
  } else if (bid < 640) {
    int t = bid - 512;
    int ccol = (t & 3) * 128, crow = (t >> 2) * 128;
    gemm_tile(a3k, w3, kk, 512, INV_SCALE, nullptr, crow, ccol, smdyn);
  } else {
    int t = bid - 640;
    int ccol = (t & 3) * 128, crow = (t >> 2) * 128;
    gemm_tile(a3v, w3 + (size_t)512 * KP, vv, 512, 1.0f, nullptr, crow, ccol, smdyn);
  }
}

// output projection GEMM
__global__ __launch_bounds__(256, 2) void gemm_wd(
    const __nv_bfloat16* __restrict__ a3, const __nv_bfloat16* __restrict__ w3,
    float* __restrict__ out) {
  extern __shared__ __align__(128) char smdyn[];
  gemm_tile(a3, w3 + (size_t)3072 * KP, out, 2048, 1.0f, nullptr,
            blockIdx.y * 128, blockIdx.x * 128, smdyn);
}

// ================= scan pass A: composed chunk maps =================
__global__ void amat_kernel() {
  int c = blockIdx.x;
  int b = threadIdx.x;
  float s[NSLOTS];
#pragma unroll
  for (int j = 0; j < NSLOTS; j++) s[j] = (j == b) ? 1.f : 0.f;
  int t0 = c * CLEN;
  for (int t = t0; t < t0 + CLEN; t++) {
    gate_step(s, key_div4(t));
    s[0] = 0.f;
  }
#pragma unroll
  for (int j = 0; j < NSLOTS; j++) d_amat[(c * NSLOTS + j) * NSLOTS + b] = s[j];
}

// ================= scan pass 1: local scans =================
__global__ __launch_bounds__(128) void scan_pass1() {
  int c = blockIdx.x;
  int g = blockIdx.y * 128 + threadIdx.x;
  const float* src = (g < 512) ? (d_kk + g) : (d_vv + (g - 512));
  float s[NSLOTS];
#pragma unroll
  for (int j = 0; j < NSLOTS; j++) s[j] = 0.f;
  int t0 = c * CLEN;
  for (int t = t0; t < t0 + CLEN; t++) {
    gate_step(s, key_div4(t));
    s[0] = src[(size_t)t * 512];
  }
#pragma unroll
  for (int j = 0; j < NSLOTS; j++) d_lend[(c * NDIMS + g) * NSLOTS + j] = s[j];
}

// ================= scan pass 2: carry propagation =================
__global__ __launch_bounds__(256) void scan_pass2() {
  int g = blockIdx.x * 8 + (threadIdx.x >> 5);
  int j = threadIdx.x & 31;
  float carry = 0.f;
  for (int c = 0; c < NCHUNK; c++) {
    d_carryb[(c * NDIMS + g) * NSLOTS + j] = carry;
    float nc = d_lend[(c * NDIMS + g) * NSLOTS + j];
    const float* arow = &d_amat[(c * NSLOTS + j) * NSLOTS];
#pragma unroll
    for (int i = 0; i < NSLOTS; i++) {
      float ci = __shfl_sync(0xffffffffu, carry, i);
      nc = fmaf(arow[i], ci, nc);
    }
    carry = nc;
  }
}

// ================= fused scan + rmsnorm + attention =================
// 3 syncs/timestep. Norms computed incrementally by state-owner threads
// (warp partials in phase A), assembled cheaply in phase B.
__global__ __launch_bounds__(256) void scan_attn_kernel(
    const float* __restrict__ key_pos, const float* __restrict__ ln_k_w,
    const float* __restrict__ ln_v_w, __nv_bfloat16* __restrict__ out) {
  __shared__ float ksh[NSLOTS][KPITCH];
  __shared__ float vsh[NSLOTS][KPITCH];
  __shared__ float qsh[4 * 128];
  __shared__ float pk[4][NSLOTS];        // per-warp k norm partials
  __shared__ float pv[4][NSLOTS];        // per-warp v norm partials
  __shared__ float ssk_s[NSLOTS];        // running k norm (sum of squares)
  __shared__ float vsc[NSLOTS];          // running v inverse rms
  __shared__ float psh[4][NSLOTS];
  __shared__ float lnv[128];

  const int c = blockIdx.x;
  const int kv = blockIdx.y;
  const int tid = threadIdx.x;
  const int d = tid & 127;
  const bool isV = tid >= 128;
  const int warp = tid >> 5;
  const int lane = tid & 31;

  if (isV) lnv[d] = ln_v_w[d];

  const int g = isV ? (512 + kv * 128 + d) : (kv * 128 + d);
  float s[NSLOTS];
  const float* carry = &d_carryb[(c * NDIMS + g) * NSLOTS];
#pragma unroll
  for (int j = 0; j < NSLOTS; j++) s[j] = carry[j];

  float kp[NSLOTS];
  if (!isV) {
#pragma unroll
    for (int j = 0; j < NSLOTS; j++) kp[j] = key_pos[d * NSLOTS + j];
  } else {
#pragma unroll
    for (int j = 0; j < NSLOTS; j++) kp[j] = 0.f;
  }

  // pre-chunk store of all 32 slots + seed all norm partials
  float* col = isV ? &vsh[0][d] : &ksh[0][d];
  float* pout = isV ? &pv[warp - 4][0] : &pk[warp][0];
#pragma unroll
  for (int j = 0; j < NSLOTS; j++) {
    float val = s[j] + kp[j];
    col[j * KPITCH] = val;
    norm_part(val, pout, j, lane);
  }

  const float* src = isV ? &d_vv[kv * 128 + d] : &d_kk[kv * 128 + d];
  const float* qrow = &d_qq[(size_t)(c * CLEN) * 2048 + kv * 512];
  const float lnkA = ln_k_w[(tid * 2) & 127];
  const float lnkB = ln_k_w[(tid * 2 + 1) & 127];

  const int t0 = c * CLEN;
  float x_next = src[(size_t)t0 * 512];
  float2 q_next = *(const float2*)&qrow[tid * 2];

  for (int it = 0; it < CLEN; it++) {
    const int t = t0 + it;
    const int kdiv = key_div4(t);
    const float x = x_next;
    const float2 qv = q_next;
    const int itn = (it + 1 < CLEN) ? it + 1 : it;
    x_next = src[(size_t)(t0 + itn) * 512];
    q_next = *(const float2*)&qrow[(size_t)itn * 2048 + tid * 2];

    // --- phase A: recurrence + store + norm partials for changed slots; q stage ---
    switch (kdiv) {
      case 1: step_store_norm<4>(s, kp, col, x, pout, lane); break;
      case 2: step_store_norm<8>(s, kp, col, x, pout, lane); break;
      case 3: step_store_norm<12>(s, kp, col, x, pout, lane); break;
      case 4: step_store_norm<16>(s, kp, col, x, pout, lane); break;
      case 5: step_store_norm<20>(s, kp, col, x, pout, lane); break;
      case 6: step_store_norm<24>(s, kp, col, x, pout, lane); break;
      case 7: step_store_norm<28>(s, kp, col, x, pout, lane); break;
      default: step_store_norm<32>(s, kp, col, x, pout, lane); break;
    }
    qsh[tid * 2] = qv.x * lnkA;
    qsh[tid * 2 + 1] = qv.y * lnkB;
    __syncthreads();

    const int jm = (it == 0) ? 31 : min(kdiv * 4, 31);

    // --- phase B: warps 0-3 logits + softmax; warp 4 assembles vsc ---
    if (warp < 4) {
      const int e = lane;
      float ssk;
      if (e <= jm) {
        ssk = pk[0][e] + pk[1][e] + pk[2][e] + pk[3][e];
        if (warp == 0) ssk_s[e] = ssk;       // persist (disjoint from reads below)
      } else {
        ssk = ssk_s[e];
      }
      const float rinv = rsqrtf(ssk * (1.0f / 128.0f) + EPSF);

      const float4* qv4 = (const float4*)&qsh[warp * 128];
      const float* kr = &ksh[e][0];
      float acc0 = 0.f, acc1 = 0.f;
#pragma unroll
      for (int i = 0; i < 16; i++) {
        float4 a0 = qv4[2 * i], a1 = qv4[2 * i + 1];
        float b0 = kr[8 * i], b1 = kr[8 * i + 1], b2 = kr[8 * i + 2], b3 = kr[8 * i + 3];
        float b4 = kr[8 * i + 4], b5 = kr[8 * i + 5], b6 = kr[8 * i + 6], b7 = kr[8 * i + 7];
        acc0 = fmaf(a0.x, b0, acc0); acc1 = fmaf(a0.y, b1, acc1);
        acc0 = fmaf(a0.z, b2, acc0); acc1 = fmaf(a0.w, b3, acc1);
        acc0 = fmaf(a1.x, b4, acc0); acc1 = fmaf(a1.y, b5, acc1);
        acc0 = fmaf(a1.z, b6, acc0); acc1 = fmaf(a1.w, b7, acc1);
      }
      float l = (acc0 + acc1) * rinv;
      float m = l;
#pragma unroll
      for (int off = 16; off; off >>= 1) m = fmaxf(m, __shfl_xor_sync(0xffffffffu, m, off));
      float p = __expf(l - m);
      float sum = p;
#pragma unroll
      for (int off = 16; off; off >>= 1) sum += __shfl_xor_sync(0xffffffffu, sum, off);
      psh[warp][e] = p / sum;
    } else if (warp == 4) {
      if (lane <= jm) {
        float ssv = pv[0][lane] + pv[1][lane] + pv[2][lane] + pv[3][lane];
        vsc[lane] = rsqrtf(ssv * (1.0f / 128.0f) + EPSF);
      }
    }
    __syncthreads();

    // --- phase C: AV + direct bf16 split store ---
    {
      const int hx = (tid >> 7) * 2;
      float a0 = 0.f, a1 = 0.f, a2 = 0.f, a3 = 0.f;
#pragma unroll
      for (int e = 0; e < NSLOTS; e += 2) {
        float vv0 = vsh[e][d] * vsc[e];
        float vv1 = vsh[e + 1][d] * vsc[e + 1];
        a0 = fmaf(psh[hx][e], vv0, a0);
        a1 = fmaf(psh[hx + 1][e], vv0, a1);
        a2 = fmaf(psh[hx][e + 1], vv1, a2);
        a3 = fmaf(psh[hx + 1][e + 1], vv1, a3);
      }
      a0 += a2; a1 += a3;
      const float w = lnv[d];
      a0 *= w; a1 *= w;
      __nv_bfloat16* row = out + (size_t)t * KP;
      const int c0 = kv * 512 + hx * 128 + d;
      __nv_bfloat16 h, l;
      split_bf16(a0, h, l);
      row[c0] = h; row[c0 + 2048] = l; row[c0 + 4096] = h;
      split_bf16(a1, h, l);
      row[c0 + 128] = h; row[c0 + 128 + 2048] = l; row[c0 + 128 + 4096] = h;
    }
    __syncthreads();
  }
}

// ================= launch =================
extern "C" void kernel_launch(void* const* d_in, const int* in_sizes, int n_in,
                              void* d_out, int out_size) {
  const float* q        = (const float*)d_in[0];
  const float* k        = (const float*)d_in[1];
  const float* v        = (const float*)d_in[2];
  const float* wq       = (const float*)d_in[3];
  const float* wk       = (const float*)d_in[4];
  const float* wv       = (const float*)d_in[5];
  const float* wd       = (const float*)d_in[6];
  const float* key_pos  = (const float*)d_in[7];
  const float* query_pos= (const float*)d_in[8];
  const float* ln_k_w   = (const float*)d_in[9];
  const float* ln_v_w   = (const float*)d_in[10];

  float *p_kk, *p_vv, *p_qq;
  __nv_bfloat16 *p_a3, *p_a3k, *p_a3v, *p_w3;
  cudaGetSymbolAddress((void**)&p_kk, d_kk);
  cudaGetSymbolAddress((void**)&p_vv, d_vv);
  cudaGetSymbolAddress((void**)&p_qq, d_qq);
  cudaGetSymbolAddress((void**)&p_a3, d_a3);
  cudaGetSymbolAddress((void**)&p_a3k, d_a3k);
  cudaGetSymbolAddress((void**)&p_a3v, d_a3v);
  cudaGetSymbolAddress((void**)&p_w3, d_w3);

  cudaFuncSetAttribute(gemm_qkv, cudaFuncAttributeMaxDynamicSharedMemorySize, GSMEM);
  cudaFuncSetAttribute(gemm_wd, cudaFuncAttributeMaxDynamicSharedMemorySize, GSMEM);

  // 1: all weight splits
  split_wt_all<<<dim3(64, 64, 4), 256>>>(wk, wv, wq, wd, p_w3);
  // 2: all activation splits
  split_act_all<<<dim3(LSEQ * EMB / 4 / 256, 1, 3), 256>>>(q, k, v, p_a3, p_a3k, p_a3v);
  // 3: composed chunk gate maps
  amat_kernel<<<NCHUNK, 32>>>();
  // 4 (PROFILED): merged q+k+v projection GEMM
  gemm_qkv<<<768, 256, GSMEM>>>(p_a3, p_a3k, p_a3v, p_w3, p_qq, p_kk, p_vv, query_pos);
  // 5-6: scan carry setup
  scan_pass1<<<dim3(NCHUNK, 8), 128>>>();
  scan_pass2<<<128, 256>>>();
  // 7: fused re-scan + rmsnorm + attention
  scan_attn_kernel<<<dim3(NCHUNK, KVHEADS), 256>>>(key_pos, ln_k_w, ln_v_w, p_a3);
  // 8: output projection
  gemm_wd<<<dim3(2048 / 128, LSEQ / 128), 256, GSMEM>>>(p_a3, p_w3, (float*)d_out);
}

// round 14
// speedup vs baseline: 1.6302x; 1.6302x over previous
#include <cuda_runtime.h>
#include <cuda_bf16.h>
#include <cstdint>
#include <math.h>

// ================= problem constants =================
#define LSEQ 4096
#define EMB 2048
#define KVHEADS 4
#define NSLOTS 32
#define NDIMS 1024
#define NCHUNK 128
#define CLEN 32                          // LSEQ / NCHUNK
#define RHALF 0.70710678118654752f
#define INV_SCALE 0.29730177875068026f   // 1 / 128^0.25
#define EPSF 1e-6f
#define KP 6144                          // K' = 3 * 2048 (hi|lo|hi concat)
#define KPITCH 133                       // bank step 5 (coprime 32): conflict-free cols

// ================= device scratch =================
__device__ float d_kk[LSEQ * 512];
__device__ float d_vv[LSEQ * 512];
__device__ float d_qq[LSEQ * 2048];
__device__ float d_lend[NCHUNK * NDIMS * NSLOTS];
__device__ float d_carryb[NCHUNK * NDIMS * NSLOTS];
__device__ float d_amat[NCHUNK * NSLOTS * NSLOTS];
__device__ __nv_bfloat16 d_a3[(size_t)LSEQ * KP];     // q split, later attn split
__device__ __nv_bfloat16 d_a3k[(size_t)LSEQ * KP];    // k split
__device__ __nv_bfloat16 d_a3v[(size_t)LSEQ * KP];    // v split
__device__ __nv_bfloat16 d_w3[(size_t)5120 * KP];
// d_w3 rows: wk@0 (512), wv@512, wq@1024 (2048), wd@3072 (2048)

// ================= gate recurrence =================
template <int KEY>
__device__ __forceinline__ void merge_shift(float (&s)[NSLOTS]) {
  s[KEY] = RHALF * (s[KEY] + s[KEY - 1]);
#pragma unroll
  for (int j = KEY - 1; j >= 1; --j) s[j] = s[j - 1];
}

__device__ __forceinline__ void gate_step(float (&s)[NSLOTS], int kdiv) {
  switch (kdiv) {
    case 1: merge_shift<4>(s); break;
    case 2: merge_shift<8>(s); break;
    case 3: merge_shift<12>(s); break;
    case 4: merge_shift<16>(s); break;
    case 5: merge_shift<20>(s); break;
    case 6: merge_shift<24>(s); break;
    case 7: merge_shift<28>(s); break;
    default:
#pragma unroll
      for (int j = 31; j >= 1; --j) s[j] = s[j - 1];
      break;
  }
}

__device__ __forceinline__ int key_div4(int t) { return __ffs(~(t & 1023)); }

template <int KEY>
__device__ __forceinline__ void step_store(float (&s)[NSLOTS], const float (&kp)[NSLOTS],
                                           float* col, float x) {
  if (KEY < 32) {
    s[KEY] = RHALF * (s[KEY] + s[KEY - 1]);
    col[KEY * KPITCH] = s[KEY] + kp[KEY];
  }
  constexpr int TOP = (KEY < 32) ? KEY : 32;
#pragma unroll
  for (int j = TOP - 1; j >= 1; --j) {
    s[j] = s[j - 1];
    col[j * KPITCH] = s[j] + kp[j];
  }
  s[0] = x;
  col[0] = x + kp[0];
}

// ================= split helpers =================
__device__ __forceinline__ void split_bf16(float x, __nv_bfloat16& h, __nv_bfloat16& l) {
  h = __float2bfloat16_rn(x);
  l = __float2bfloat16_rn(x - __bfloat162float(h));
}

// all three activation splits in one launch: z = 0:q, 1:k, 2:v
__global__ __launch_bounds__(256) void split_act_all(
    const float* __restrict__ q, const float* __restrict__ k,
    const float* __restrict__ v, __nv_bfloat16* __restrict__ dq,
    __nv_bfloat16* __restrict__ dk, __nv_bfloat16* __restrict__ dv) {
  const int K = EMB;
  const float* src = (blockIdx.z == 0) ? q : (blockIdx.z == 1) ? k : v;
  __nv_bfloat16* dst = (blockIdx.z == 0) ? dq : (blockIdx.z == 1) ? dk : dv;
  int idx = blockIdx.x * 256 + threadIdx.x;
  float4 vv = ((const float4*)src)[idx];
  int c = (idx % (K / 4)) * 4;
  int r = idx / (K / 4);
  __nv_bfloat16 h0, l0, h1, l1, h2, l2, h3, l3;
  split_bf16(vv.x, h0, l0); split_bf16(vv.y, h1, l1);
  split_bf16(vv.z, h2, l2); split_bf16(vv.w, h3, l3);
  __nv_bfloat162 hA(h0, h1), hB(h2, h3), lA(l0, l1), lB(l2, l3);
  __nv_bfloat16* base = dst + (size_t)r * KP + c;
  *(__nv_bfloat162*)(base) = hA;            *(__nv_bfloat162*)(base + 2) = hB;
  *(__nv_bfloat162*)(base + K) = lA;        *(__nv_bfloat162*)(base + K + 2) = lB;
  *(__nv_bfloat162*)(base + 2 * K) = hA;    *(__nv_bfloat162*)(base + 2 * K + 2) = hB;
}

// all four weight splits in one launch: z = 0:wk, 1:wv, 2:wq, 3:wd
__global__ __launch_bounds__(256) void split_wt_all(
    const float* __restrict__ wk, const float* __restrict__ wv,
    const float* __restrict__ wq, const float* __restrict__ wd,
    __nv_bfloat16* __restrict__ w3) {
  const int K = EMB;
  const int z = blockIdx.z;
  const int N = (z < 2) ? 512 : 2048;
  if (blockIdx.x * 32 >= N) return;
  const float* src = (z == 0) ? wk : (z == 1) ? wv : (z == 2) ? wq : wd;
  __nv_bfloat16* dst = w3 + ((z == 0) ? 0 : (z == 1) ? (size_t)512 * KP
                            : (z == 2) ? (size_t)1024 * KP : (size_t)3072 * KP);
  __shared__ float tile[32][33];
  int n0 = blockIdx.x * 32, k0 = blockIdx.y * 32;
  int tx = threadIdx.x & 31, ty = threadIdx.x >> 5;
#pragma unroll
  for (int i = 0; i < 4; i++)
    tile[ty + 8 * i][tx] = src[(size_t)(k0 + ty + 8 * i) * N + n0 + tx];
  __syncthreads();
#pragma unroll
  for (int i = 0; i < 4; i++) {
    int n = n0 + ty + 8 * i;
    int kk = k0 + tx;
    float x = tile[tx][ty + 8 * i];
    __nv_bfloat16 h, l;
    split_bf16(x, h, l);
    __nv_bfloat16* base = dst + (size_t)n * KP;
    base[kk] = h; base[K + kk] = h; base[2 * K + kk] = l;
  }
}

// ================= bf16 tensor-core GEMM core =================
#define BKC 64
#define GKT (KP / BKC)                  // 96 k-chunks
#define SPITCH 72
#define OPBYTES (128 * SPITCH * 2)
#define STG_BYTES (2 * OPBYTES)
#define GSMEM (3 * STG_BYTES)

__device__ __forceinline__ void mma16816(float (&c)[4], const unsigned (&a)[4],
                                         unsigned b0, unsigned b1) {
  asm volatile(
      "mma.sync.aligned.m16n8k16.row.col.f32.bf16.bf16.f32 "
      "{%0,%1,%2,%3}, {%4,%5,%6,%7}, {%8,%9}, {%0,%1,%2,%3};"
      : "+f"(c[0]), "+f"(c[1]), "+f"(c[2]), "+f"(c[3])
      : "r"(a[0]), "r"(a[1]), "r"(a[2]), "r"(a[3]), "r"(b0), "r"(b1));
}

#define CP16(dst, src) \
  asm volatile("cp.async.cg.shared.global [%0], [%1], 16;" :: "r"(dst), "l"(src))

__device__ __forceinline__ void gemm_tile(
    const __nv_bfloat16* __restrict__ A, const __nv_bfloat16* __restrict__ Bn,
    float* __restrict__ C, int N, float alpha, const float* __restrict__ bias,
    int crow, int ccol, char* smdyn) {
  const int tid = threadIdx.x;
  const int lane = tid & 31, warp = tid >> 5;
  const int wm = (warp & 1) * 64, wn = (warp >> 1) * 32;
  const int g = lane >> 2, t = lane & 3;

  const unsigned sBase = (unsigned)__cvta_generic_to_shared(smdyn);

  const int lrow = tid >> 3;
  const int lcc = (tid & 7) * 8;
  const __nv_bfloat16* gA = A + (size_t)(crow + lrow) * KP + lcc;
  const __nv_bfloat16* gB = Bn + (size_t)(ccol + lrow) * KP + lcc;
  const unsigned oA = (lrow * SPITCH + lcc) * 2;
  const unsigned oB = OPBYTES + (lrow * SPITCH + lcc) * 2;

  float acc[4][4][4];
#pragma unroll
  for (int i = 0; i < 4; i++)
#pragma unroll
    for (int j = 0; j < 4; j++)
#pragma unroll
      for (int r = 0; r < 4; r++) acc[i][j][r] = 0.f;

  const int a_row = wm + (lane & 15);
  const int a_kof = (lane >> 4) << 3;
  const int b_row = wn + ((lane >> 4) << 3) + (lane & 7);
  const int b_kof = ((lane >> 3) & 1) << 3;

#pragma unroll
  for (int p = 0; p < 2; p++) {
    const unsigned so = sBase + p * STG_BYTES;
    const __nv_bfloat16* pa = gA + (size_t)p * BKC;
    const __nv_bfloat16* pb = gB + (size_t)p * BKC;
#pragma unroll
    for (int i = 0; i < 4; i++) {
      CP16(so + oA + i * 32 * SPITCH * 2, pa + (size_t)(i * 32) * KP);
      CP16(so + oB + i * 32 * SPITCH * 2, pb + (size_t)(i * 32) * KP);
    }
    asm volatile("cp.async.commit_group;");
  }

  int st = 0;
  for (int kt = 0; kt < GKT; kt++) {
    if (kt + 2 < GKT) asm volatile("cp.async.wait_group 1;");
    else              asm volatile("cp.async.wait_group 0;");
    __syncthreads();

    if (kt + 2 < GKT) {
      int ns = st + 2; if (ns >= 3) ns -= 3;
      const unsigned so = sBase + ns * STG_BYTES;
      const __nv_bfloat16* pa = gA + (size_t)(kt + 2) * BKC;
      const __nv_bfloat16* pb = gB + (size_t)(kt + 2) * BKC;
#pragma unroll
      for (int i = 0; i < 4; i++) {
        CP16(so + oA + i * 32 * SPITCH * 2, pa + (size_t)(i * 32) * KP);
        CP16(so + oB + i * 32 * SPITCH * 2, pb + (size_t)(i * 32) * KP);
      }
      asm volatile("cp.async.commit_group;");
    }

    const unsigned sA = sBase + st * STG_BYTES;
    const unsigned sB = sA + OPBYTES;
#pragma unroll
    for (int ks = 0; ks < 4; ks++) {
      const int k0 = ks * 16;
      unsigned a[4][4];
#pragma unroll
      for (int i = 0; i < 4; i++) {
        unsigned addr = sA + (((a_row + i * 16) * SPITCH) + k0 + a_kof) * 2;
        asm volatile(
            "ldmatrix.sync.aligned.m8n8.x4.shared.b16 {%0,%1,%2,%3}, [%4];"
            : "=r"(a[i][0]), "=r"(a[i][1]), "=r"(a[i][2]), "=r"(a[i][3])
            : "r"(addr));
      }
      unsigned b[4][2];
#pragma unroll
      for (int jj = 0; jj < 2; jj++) {
        unsigned addr = sB + (((b_row + jj * 16) * SPITCH) + k0 + b_kof) * 2;
        asm volatile(
            "ldmatrix.sync.aligned.m8n8.x4.shared.b16 {%0,%1,%2,%3}, [%4];"
            : "=r"(b[2 * jj][0]), "=r"(b[2 * jj][1]),
              "=r"(b[2 * jj + 1][0]), "=r"(b[2 * jj + 1][1])
            : "r"(addr));
      }
#pragma unroll
      for (int i = 0; i < 4; i++)
#pragma unroll
        for (int j = 0; j < 4; j++) mma16816(acc[i][j], a[i], b[j][0], b[j][1]);
    }
    if (++st == 3) st = 0;
  }

#pragma unroll
  for (int i = 0; i < 4; i++) {
#pragma unroll
    for (int j = 0; j < 4; j++) {
      int row = crow + wm + i * 16 + g;
      int col = ccol + wn + j * 8 + 2 * t;
      float b0 = bias ? bias[col & 127] : 0.f;
      float b1 = bias ? bias[(col + 1) & 127] : 0.f;
      float2 v0 = make_float2(alpha * acc[i][j][0] + b0, alpha * acc[i][j][1] + b1);
      float2 v1 = make_float2(alpha * acc[i][j][2] + b0, alpha * acc[i][j][3] + b1);
      *(float2*)(C + (size_t)row * N + col) = v0;
      *(float2*)(C + (size_t)(row + 8) * N + col) = v1;
    }
  }
}

// merged q+k+v projection GEMM: 768 CTAs
__global__ __launch_bounds__(256, 2) void gemm_qkv(
    const __nv_bfloat16* __restrict__ a3q, const __nv_bfloat16* __restrict__ a3k,
    const __nv_bfloat16* __restrict__ a3v, const __nv_bfloat16* __restrict__ w3,
    float* __restrict__ qq, float* __restrict__ kk, float* __restrict__ vv,
    const float* __restrict__ query_pos) {
  extern __shared__ __align__(128) char smdyn[];
  const int bid = blockIdx.x;
  if (bid < 512) {
    int ccol = (bid & 15) * 128, crow = (bid >> 4) * 128;
    gemm_tile(a3q, w3 + (size_t)1024 * KP, qq, 2048, INV_SCALE, query_pos,
              crow, ccol, smdyn);
  } else if (bid < 640) {
    int t = bid - 512;
    int ccol = (t & 3) * 128, crow = (t >> 2) * 128;
    gemm_tile(a3k, w3, kk, 512, INV_SCALE, nullptr, crow, ccol, smdyn);
  } else {
    int t = bid - 640;
    int ccol = (t & 3) * 128, crow = (t >> 2) * 128;
    gemm_tile(a3v, w3 + (size_t)512 * KP, vv, 512, 1.0f, nullptr, crow, ccol, smdyn);
  }
}

// output projection GEMM
__global__ __launch_bounds__(256, 2) void gemm_wd(
    const __nv_bfloat16* __restrict__ a3, const __nv_bfloat16* __restrict__ w3,
    float* __restrict__ out) {
  extern __shared__ __align__(128) char smdyn[];
  gemm_tile(a3, w3 + (size_t)3072 * KP, out, 2048, 1.0f, nullptr,
            blockIdx.y * 128, blockIdx.x * 128, smdyn);
}

// ================= scan pass A: composed chunk maps =================
__global__ void amat_kernel() {
  int c = blockIdx.x;
  int b = threadIdx.x;
  float s[NSLOTS];
#pragma unroll
  for (int j = 0; j < NSLOTS; j++) s[j] = (j == b) ? 1.f : 0.f;
  int t0 = c * CLEN;
  for (int t = t0; t < t0 + CLEN; t++) {
    gate_step(s, key_div4(t));
    s[0] = 0.f;
  }
#pragma unroll
  for (int j = 0; j < NSLOTS; j++) d_amat[(c * NSLOTS + j) * NSLOTS + b] = s[j];
}

// ================= scan pass 1: local scans =================
__global__ __launch_bounds__(128) void scan_pass1() {
  int c = blockIdx.x;
  int g = blockIdx.y * 128 + threadIdx.x;
  const float* src = (g < 512) ? (d_kk + g) : (d_vv + (g - 512));
  float s[NSLOTS];
#pragma unroll
  for (int j = 0; j < NSLOTS; j++) s[j] = 0.f;
  int t0 = c * CLEN;
  for (int t = t0; t < t0 + CLEN; t++) {
    gate_step(s, key_div4(t));
    s[0] = src[(size_t)t * 512];
  }
#pragma unroll
  for (int j = 0; j < NSLOTS; j++) d_lend[(c * NDIMS + g) * NSLOTS + j] = s[j];
}

// ================= scan pass 2: carry propagation =================
__global__ __launch_bounds__(256) void scan_pass2() {
  int g = blockIdx.x * 8 + (threadIdx.x >> 5);
  int j = threadIdx.x & 31;
  float carry = 0.f;
  for (int c = 0; c < NCHUNK; c++) {
    d_carryb[(c * NDIMS + g) * NSLOTS + j] = carry;
    float nc = d_lend[(c * NDIMS + g) * NSLOTS + j];
    const float* arow = &d_amat[(c * NSLOTS + j) * NSLOTS];
#pragma unroll
    for (int i = 0; i < NSLOTS; i++) {
      float ci = __shfl_sync(0xffffffffu, carry, i);
      nc = fmaf(arow[i], ci, nc);
    }
    carry = nc;
  }
}

// ================= fused scan + rmsnorm + attention (R12 structure) =================
// 3 syncs/timestep: [step_store + q] | [logits(+k-rms fused) & v-rms] | [AV]
__global__ __launch_bounds__(256) void scan_attn_kernel(
    const float* __restrict__ key_pos, const float* __restrict__ ln_k_w,
    const float* __restrict__ ln_v_w, __nv_bfloat16* __restrict__ out) {
  __shared__ float ksh[NSLOTS][KPITCH];
  __shared__ float vsh[NSLOTS][KPITCH];
  __shared__ float qsh[4 * 128];
  __shared__ float vsc[NSLOTS];
  __shared__ float psh[4][NSLOTS];
  __shared__ float lnv[128];

  const int c = blockIdx.x;
  const int kv = blockIdx.y;
  const int tid = threadIdx.x;
  const int d = tid & 127;
  const bool isV = tid >= 128;
  const int warp = tid >> 5;
  const int lane = tid & 31;

  if (isV) lnv[d] = ln_v_w[d];

  const int g = isV ? (512 + kv * 128 + d) : (kv * 128 + d);
  float s[NSLOTS];
  const float* carry = &d_carryb[(c * NDIMS + g) * NSLOTS];
#pragma unroll
  for (int j = 0; j < NSLOTS; j++) s[j] = carry[j];

  float kp[NSLOTS];
  if (!isV) {
#pragma unroll
    for (int j = 0; j < NSLOTS; j++) kp[j] = key_pos[d * NSLOTS + j];
  } else {
#pragma unroll
    for (int j = 0; j < NSLOTS; j++) kp[j] = 0.f;
  }

  float* col = isV ? &vsh[0][d] : &ksh[0][d];
#pragma unroll
  for (int j = 0; j < NSLOTS; j++) col[j * KPITCH] = s[j] + kp[j];

  const float* src = isV ? &d_vv[kv * 128 + d] : &d_kk[kv * 128 + d];
  const float* qrow = &d_qq[(size_t)(c * CLEN) * 2048 + kv * 512];
  const float lnkA = ln_k_w[(tid * 2) & 127];
  const float lnkB = ln_k_w[(tid * 2 + 1) & 127];

  const int t0 = c * CLEN;
  float x_next = src[(size_t)t0 * 512];
  float2 q_next = *(const float2*)&qrow[tid * 2];

  for (int it = 0; it < CLEN; it++) {
    const int t = t0 + it;
    const int kdiv = key_div4(t);
    const float x = x_next;
    const float2 qv = q_next;
    const int itn = (it + 1 < CLEN) ? it + 1 : it;
    x_next = src[(size_t)(t0 + itn) * 512];
    q_next = *(const float2*)&qrow[(size_t)itn * 2048 + tid * 2];

    // --- phase A: recurrence step + store changed slots; stage q ---
    switch (kdiv) {
      case 1: step_store<4>(s, kp, col, x); break;
      case 2: step_store<8>(s, kp, col, x); break;
      case 3: step_store<12>(s, kp, col, x); break;
      case 4: step_store<16>(s, kp, col, x); break;
      case 5: step_store<20>(s, kp, col, x); break;
      case 6: step_store<24>(s, kp, col, x); break;
      case 7: step_store<28>(s, kp, col, x); break;
      default: step_store<32>(s, kp, col, x); break;
    }
    qsh[tid * 2] = qv.x * lnkA;
    qsh[tid * 2 + 1] = qv.y * lnkB;
    __syncthreads();

    // --- phase B: warps 0-3 fused logits + k-rms + softmax; warps 4-7 v-rms ---
    if (warp < 4) {
      const int e = lane;
      const float4* qv4 = (const float4*)&qsh[warp * 128];
      const float* kr = &ksh[e][0];   // pitch 133: conflict-free scalar column reads
      float acc0 = 0.f, acc1 = 0.f, ss0 = 0.f, ss1 = 0.f;
#pragma unroll
      for (int i = 0; i < 32; i++) {
        float4 a = qv4[i];
        float b0 = kr[4 * i], b1 = kr[4 * i + 1], b2 = kr[4 * i + 2], b3 = kr[4 * i + 3];
        acc0 = fmaf(a.x, b0, acc0); ss0 = fmaf(b0, b0, ss0);
        acc1 = fmaf(a.y, b1, acc1); ss1 = fmaf(b1, b1, ss1);
        acc0 = fmaf(a.z, b2, acc0); ss0 = fmaf(b2, b2, ss0);
        acc1 = fmaf(a.w, b3, acc1); ss1 = fmaf(b3, b3, ss1);
      }
      float acc = acc0 + acc1;
      float ss = ss0 + ss1;
      float l = acc * rsqrtf(ss * (1.0f / 128.0f) + EPSF);
      float m = l;
#pragma unroll
      for (int off = 16; off; off >>= 1) m = fmaxf(m, __shfl_xor_sync(0xffffffffu, m, off));
      float p = __expf(l - m);
      float sum = p;
#pragma unroll
      for (int off = 16; off; off >>= 1) sum += __shfl_xor_sync(0xffffffffu, sum, off);
      psh[warp][e] = p / sum;
    } else {
      const int jm = (it == 0) ? 31 : min(kdiv * 4, 31);
      const int base = (warp - 4) * 8;
#pragma unroll
      for (int i = 0; i < 8; i++) {
        const int j = base + i;
        if (j <= jm) {
          float x0 = vsh[j][lane], x1 = vsh[j][lane + 32];
          float x2 = vsh[j][lane + 64], x3 = vsh[j][lane + 96];
          float ss = fmaf(x0, x0, fmaf(x1, x1, fmaf(x2, x2, x3 * x3)));
#pragma unroll
          for (int off = 16; off; off >>= 1) ss += __shfl_xor_sync(0xffffffffu, ss, off);
          if (lane == 0) vsc[j] = rsqrtf(ss * (1.0f / 128.0f) + EPSF);
        }
      }
    }
    __syncthreads();

    // --- phase C: AV + direct bf16 split store ---
    {
      const int hx = (tid >> 7) * 2;
      float a0 = 0.f, a1 = 0.f, a2 = 0.f, a3 = 0.f;
#pragma unroll
      for (int e = 0; e < NSLOTS; e += 2) {
        float vv0 = vsh[e][d] * vsc[e];
        float vv1 = vsh[e + 1][d] * vsc[e + 1];
        a0 = fmaf(psh[hx][e], vv0, a0);
        a1 = fmaf(psh[hx + 1][e], vv0, a1);
        a2 = fmaf(psh[hx][e + 1], vv1, a2);
        a3 = fmaf(psh[hx + 1][e + 1], vv1, a3);
      }
      a0 += a2; a1 += a3;
      const float w = lnv[d];
      a0 *= w; a1 *= w;
      __nv_bfloat16* row = out + (size_t)t * KP;
      const int c0 = kv * 512 + hx * 128 + d;
      __nv_bfloat16 h, l;
      split_bf16(a0, h, l);
      row[c0] = h; row[c0 + 2048] = l; row[c0 + 4096] = h;
      split_bf16(a1, h, l);
      row[c0 + 128] = h; row[c0 + 128 + 2048] = l; row[c0 + 128 + 4096] = h;
    }
    __syncthreads();
  }
}

// ================= launch =================
extern "C" void kernel_launch(void* const* d_in, const int* in_sizes, int n_in,
                              void* d_out, int out_size) {
  const float* q        = (const float*)d_in[0];
  const float* k        = (const float*)d_in[1];
  const float* v        = (const float*)d_in[2];
  const float* wq       = (const float*)d_in[3];
  const float* wk       = (const float*)d_in[4];
  const float* wv       = (const float*)d_in[5];
  const float* wd       = (const float*)d_in[6];
  const float* key_pos  = (const float*)d_in[7];
  const float* query_pos= (const float*)d_in[8];
  const float* ln_k_w   = (const float*)d_in[9];
  const float* ln_v_w   = (const float*)d_in[10];

  float *p_kk, *p_vv, *p_qq;
  __nv_bfloat16 *p_a3, *p_a3k, *p_a3v, *p_w3;
  cudaGetSymbolAddress((void**)&p_kk, d_kk);
  cudaGetSymbolAddress((void**)&p_vv, d_vv);
  cudaGetSymbolAddress((void**)&p_qq, d_qq);
  cudaGetSymbolAddress((void**)&p_a3, d_a3);
  cudaGetSymbolAddress((void**)&p_a3k, d_a3k);
  cudaGetSymbolAddress((void**)&p_a3v, d_a3v);
  cudaGetSymbolAddress((void**)&p_w3, d_w3);

  cudaFuncSetAttribute(gemm_qkv, cudaFuncAttributeMaxDynamicSharedMemorySize, GSMEM);
  cudaFuncSetAttribute(gemm_wd, cudaFuncAttributeMaxDynamicSharedMemorySize, GSMEM);

  // 1: all weight splits
  split_wt_all<<<dim3(64, 64, 4), 256>>>(wk, wv, wq, wd, p_w3);
  // 2: all activation splits
  split_act_all<<<dim3(LSEQ * EMB / 4 / 256, 1, 3), 256>>>(q, k, v, p_a3, p_a3k, p_a3v);
  // 3: composed chunk gate maps
  amat_kernel<<<NCHUNK, 32>>>();
  // 4 (PROFILED): merged q+k+v projection GEMM
  gemm_qkv<<<768, 256, GSMEM>>>(p_a3, p_a3k, p_a3v, p_w3, p_qq, p_kk, p_vv, query_pos);
  // 5-6: scan carry setup
  scan_pass1<<<dim3(NCHUNK, 8), 128>>>();
  scan_pass2<<<128, 256>>>();
  // 7: fused re-scan + rmsnorm + attention
  scan_attn_kernel<<<dim3(NCHUNK, KVHEADS), 256>>>(key_pos, ln_k_w, ln_v_w, p_a3);
  // 8: output projection
  gemm_wd<<<dim3(2048 / 128, LSEQ / 128), 256, GSMEM>>>(p_a3, p_w3, (float*)d_out);
}

// round 15
// speedup vs baseline: 1.6447x; 1.0089x over previous
#include <cuda_runtime.h>
#include <cuda_bf16.h>
#include <cstdint>
#include <math.h>

// ================= problem constants =================
#define LSEQ 4096
#define EMB 2048
#define KVHEADS 4
#define NSLOTS 32
#define NDIMS 1024
#define NCHUNK 128
#define CLEN 32                          // LSEQ / NCHUNK
#define RHALF 0.70710678118654752f
#define INV_SCALE 0.29730177875068026f   // 1 / 128^0.25
#define EPSF 1e-6f
#define SKP 4096                         // stored K' width: [hi|lo] (dedup)
#define KPITCH 133                       // bank step 5 (coprime 32): conflict-free cols

// ================= device scratch =================
__device__ float d_kk[LSEQ * 512];
__device__ float d_vv[LSEQ * 512];
__device__ float d_qq[LSEQ * 2048];
__device__ float d_lend[NCHUNK * NDIMS * NSLOTS];
__device__ float d_carryb[NCHUNK * NDIMS * NSLOTS];
__device__ float d_amat[NCHUNK * NSLOTS * NSLOTS];
__device__ __nv_bfloat16 d_a3[(size_t)LSEQ * SKP];     // q split, later attn split
__device__ __nv_bfloat16 d_a3k[(size_t)LSEQ * SKP];    // k split
__device__ __nv_bfloat16 d_a3v[(size_t)LSEQ * SKP];    // v split
__device__ __nv_bfloat16 d_w3[(size_t)5120 * SKP];
// d_w3 rows: wk@0 (512), wv@512, wq@1024 (2048), wd@3072 (2048); each row [hi|lo]

// ================= gate recurrence =================
template <int KEY>
__device__ __forceinline__ void merge_shift(float (&s)[NSLOTS]) {
  s[KEY] = RHALF * (s[KEY] + s[KEY - 1]);
#pragma unroll
  for (int j = KEY - 1; j >= 1; --j) s[j] = s[j - 1];
}

__device__ __forceinline__ void gate_step(float (&s)[NSLOTS], int kdiv) {
  switch (kdiv) {
    case 1: merge_shift<4>(s); break;
    case 2: merge_shift<8>(s); break;
    case 3: merge_shift<12>(s); break;
    case 4: merge_shift<16>(s); break;
    case 5: merge_shift<20>(s); break;
    case 6: merge_shift<24>(s); break;
    case 7: merge_shift<28>(s); break;
    default:
#pragma unroll
      for (int j = 31; j >= 1; --j) s[j] = s[j - 1];
      break;
  }
}

__device__ __forceinline__ int key_div4(int t) { return __ffs(~(t & 1023)); }

template <int KEY>
__device__ __forceinline__ void step_store(float (&s)[NSLOTS], const float (&kp)[NSLOTS],
                                           float* col, float x) {
  if (KEY < 32) {
    s[KEY] = RHALF * (s[KEY] + s[KEY - 1]);
    col[KEY * KPITCH] = s[KEY] + kp[KEY];
  }
  constexpr int TOP = (KEY < 32) ? KEY : 32;
#pragma unroll
  for (int j = TOP - 1; j >= 1; --j) {
    s[j] = s[j - 1];
    col[j * KPITCH] = s[j] + kp[j];
  }
  s[0] = x;
  col[0] = x + kp[0];
}

// ================= split helpers =================
__device__ __forceinline__ void split_bf16(float x, __nv_bfloat16& h, __nv_bfloat16& l) {
  h = __float2bfloat16_rn(x);
  l = __float2bfloat16_rn(x - __bfloat162float(h));
}

// all three activation splits in one launch: z = 0:q, 1:k, 2:v ([hi|lo], width 4096)
__global__ __launch_bounds__(256) void split_act_all(
    const float* __restrict__ q, const float* __restrict__ k,
    const float* __restrict__ v, __nv_bfloat16* __restrict__ dq,
    __nv_bfloat16* __restrict__ dk, __nv_bfloat16* __restrict__ dv) {
  const int K = EMB;
  const float* src = (blockIdx.z == 0) ? q : (blockIdx.z == 1) ? k : v;
  __nv_bfloat16* dst = (blockIdx.z == 0) ? dq : (blockIdx.z == 1) ? dk : dv;
  int idx = blockIdx.x * 256 + threadIdx.x;
  float4 vv = ((const float4*)src)[idx];
  int c = (idx % (K / 4)) * 4;
  int r = idx / (K / 4);
  __nv_bfloat16 h0, l0, h1, l1, h2, l2, h3, l3;
  split_bf16(vv.x, h0, l0); split_bf16(vv.y, h1, l1);
  split_bf16(vv.z, h2, l2); split_bf16(vv.w, h3, l3);
  __nv_bfloat162 hA(h0, h1), hB(h2, h3), lA(l0, l1), lB(l2, l3);
  __nv_bfloat16* base = dst + (size_t)r * SKP + c;
  *(__nv_bfloat162*)(base) = hA;        *(__nv_bfloat162*)(base + 2) = hB;
  *(__nv_bfloat162*)(base + K) = lA;    *(__nv_bfloat162*)(base + K + 2) = lB;
}

// all four weight splits in one launch: z = 0:wk, 1:wv, 2:wq, 3:wd ([hi|lo])
__global__ __launch_bounds__(256) void split_wt_all(
    const float* __restrict__ wk, const float* __restrict__ wv,
    const float* __restrict__ wq, const float* __restrict__ wd,
    __nv_bfloat16* __restrict__ w3) {
  const int K = EMB;
  const int z = blockIdx.z;
  const int N = (z < 2) ? 512 : 2048;
  if (blockIdx.x * 32 >= N) return;
  const float* src = (z == 0) ? wk : (z == 1) ? wv : (z == 2) ? wq : wd;
  __nv_bfloat16* dst = w3 + ((z == 0) ? 0 : (z == 1) ? (size_t)512 * SKP
                            : (z == 2) ? (size_t)1024 * SKP : (size_t)3072 * SKP);
  __shared__ float tile[32][33];
  int n0 = blockIdx.x * 32, k0 = blockIdx.y * 32;
  int tx = threadIdx.x & 31, ty = threadIdx.x >> 5;
#pragma unroll
  for (int i = 0; i < 4; i++)
    tile[ty + 8 * i][tx] = src[(size_t)(k0 + ty + 8 * i) * N + n0 + tx];
  __syncthreads();
#pragma unroll
  for (int i = 0; i < 4; i++) {
    int n = n0 + ty + 8 * i;
    int kk = k0 + tx;
    float x = tile[tx][ty + 8 * i];
    __nv_bfloat16 h, l;
    split_bf16(x, h, l);
    __nv_bfloat16* base = dst + (size_t)n * SKP;
    base[kk] = h; base[K + kk] = l;
  }
}

// ================= bf16 tensor-core GEMM core =================
// Virtual K' = 6144 (96 chunks of 64). A chunks map [hi|lo|hi] -> stored [hi|lo]
// via akt = kt>=64 ? kt-64 : kt; W chunks map [hi|hi|lo] via wkt = kt<32 ? kt : kt-32.
#define BKC 64
#define GKT 96
#define SPITCH 72
#define OPBYTES (128 * SPITCH * 2)
#define STG_BYTES (2 * OPBYTES)
#define GSMEM (3 * STG_BYTES)

__device__ __forceinline__ int a_chunk(int kt) { return (kt >= 64) ? kt - 64 : kt; }
__device__ __forceinline__ int w_chunk(int kt) { return (kt < 32) ? kt : kt - 32; }

__device__ __forceinline__ void mma16816(float (&c)[4], const unsigned (&a)[4],
                                         unsigned b0, unsigned b1) {
  asm volatile(
      "mma.sync.aligned.m16n8k16.row.col.f32.bf16.bf16.f32 "
      "{%0,%1,%2,%3}, {%4,%5,%6,%7}, {%8,%9}, {%0,%1,%2,%3};"
      : "+f"(c[0]), "+f"(c[1]), "+f"(c[2]), "+f"(c[3])
      : "r"(a[0]), "r"(a[1]), "r"(a[2]), "r"(a[3]), "r"(b0), "r"(b1));
}

#define CP16(dst, src) \
  asm volatile("cp.async.cg.shared.global [%0], [%1], 16;" :: "r"(dst), "l"(src))

__device__ __forceinline__ void load_chunk(const __nv_bfloat16* gA,
                                           const __nv_bfloat16* gB, int kt,
                                           unsigned so, unsigned oA, unsigned oB) {
  const __nv_bfloat16* pa = gA + (size_t)a_chunk(kt) * BKC;
  const __nv_bfloat16* pb = gB + (size_t)w_chunk(kt) * BKC;
#pragma unroll
  for (int i = 0; i < 4; i++) {
    CP16(so + oA + i * 32 * SPITCH * 2, pa + (size_t)(i * 32) * SKP);
    CP16(so + oB + i * 32 * SPITCH * 2, pb + (size_t)(i * 32) * SKP);
  }
  asm volatile("cp.async.commit_group;");
}

__device__ __forceinline__ void gemm_tile(
    const __nv_bfloat16* __restrict__ A, const __nv_bfloat16* __restrict__ Bn,
    float* __restrict__ C, int N, float alpha, const float* __restrict__ bias,
    int crow, int ccol, char* smdyn) {
  const int tid = threadIdx.x;
  const int lane = tid & 31, warp = tid >> 5;
  const int wm = (warp & 1) * 64, wn = (warp >> 1) * 32;
  const int g = lane >> 2, t = lane & 3;

  const unsigned sBase = (unsigned)__cvta_generic_to_shared(smdyn);

  const int lrow = tid >> 3;
  const int lcc = (tid & 7) * 8;
  const __nv_bfloat16* gA = A + (size_t)(crow + lrow) * SKP + lcc;
  const __nv_bfloat16* gB = Bn + (size_t)(ccol + lrow) * SKP + lcc;
  const unsigned oA = (lrow * SPITCH + lcc) * 2;
  const unsigned oB = OPBYTES + (lrow * SPITCH + lcc) * 2;

  float acc[4][4][4];
#pragma unroll
  for (int i = 0; i < 4; i++)
#pragma unroll
    for (int j = 0; j < 4; j++)
#pragma unroll
      for (int r = 0; r < 4; r++) acc[i][j][r] = 0.f;

  const int a_row = wm + (lane & 15);
  const int a_kof = (lane >> 4) << 3;
  const int b_row = wn + ((lane >> 4) << 3) + (lane & 7);
  const int b_kof = ((lane >> 3) & 1) << 3;

  load_chunk(gA, gB, 0, sBase, oA, oB);
  load_chunk(gA, gB, 1, sBase + STG_BYTES, oA, oB);

  int st = 0;
  for (int kt = 0; kt < GKT; kt++) {
    if (kt + 2 < GKT) asm volatile("cp.async.wait_group 1;");
    else              asm volatile("cp.async.wait_group 0;");
    __syncthreads();

    if (kt + 2 < GKT) {
      int ns = st + 2; if (ns >= 3) ns -= 3;
      load_chunk(gA, gB, kt + 2, sBase + ns * STG_BYTES, oA, oB);
    }

    const unsigned sA = sBase + st * STG_BYTES;
    const unsigned sB = sA + OPBYTES;
#pragma unroll
    for (int ks = 0; ks < 4; ks++) {
      const int k0 = ks * 16;
      unsigned a[4][4];
#pragma unroll
      for (int i = 0; i < 4; i++) {
        unsigned addr = sA + (((a_row + i * 16) * SPITCH) + k0 + a_kof) * 2;
        asm volatile(
            "ldmatrix.sync.aligned.m8n8.x4.shared.b16 {%0,%1,%2,%3}, [%4];"
            : "=r"(a[i][0]), "=r"(a[i][1]), "=r"(a[i][2]), "=r"(a[i][3])
            : "r"(addr));
      }
      unsigned b[4][2];
#pragma unroll
      for (int jj = 0; jj < 2; jj++) {
        unsigned addr = sB + (((b_row + jj * 16) * SPITCH) + k0 + b_kof) * 2;
        asm volatile(
            "ldmatrix.sync.aligned.m8n8.x4.shared.b16 {%0,%1,%2,%3}, [%4];"
            : "=r"(b[2 * jj][0]), "=r"(b[2 * jj][1]),
              "=r"(b[2 * jj + 1][0]), "=r"(b[2 * jj + 1][1])
            : "r"(addr));
      }
#pragma unroll
      for (int i = 0; i < 4; i++)
#pragma unroll
        for (int j = 0; j < 4; j++) mma16816(acc[i][j], a[i], b[j][0], b[j][1]);
    }
    if (++st == 3) st = 0;
  }

#pragma unroll
  for (int i = 0; i < 4; i++) {
#pragma unroll
    for (int j = 0; j < 4; j++) {
      int row = crow + wm + i * 16 + g;
      int col = ccol + wn + j * 8 + 2 * t;
      float b0 = bias ? bias[col & 127] : 0.f;
      float b1 = bias ? bias[(col + 1) & 127] : 0.f;
      float2 v0 = make_float2(alpha * acc[i][j][0] + b0, alpha * acc[i][j][1] + b1);
      float2 v1 = make_float2(alpha * acc[i][j][2] + b0, alpha * acc[i][j][3] + b1);
      *(float2*)(C + (size_t)row * N + col) = v0;
      *(float2*)(C + (size_t)(row + 8) * N + col) = v1;
    }
  }
}

// merged q+k+v projection GEMM: 768 CTAs
__global__ __launch_bounds__(256, 2) void gemm_qkv(
    const __nv_bfloat16* __restrict__ a3q, const __nv_bfloat16* __restrict__ a3k,
    const __nv_bfloat16* __restrict__ a3v, const __nv_bfloat16* __restrict__ w3,
    float* __restrict__ qq, float* __restrict__ kk, float* __restrict__ vv,
    const float* __restrict__ query_pos) {
  extern __shared__ __align__(128) char smdyn[];
  const int bid = blockIdx.x;
  if (bid < 512) {
    int ccol = (bid & 15) * 128, crow = (bid >> 4) * 128;
    gemm_tile(a3q, w3 + (size_t)1024 * SKP, qq, 2048, INV_SCALE, query_pos,
              crow, ccol, smdyn);
  } else if (bid < 640) {
    int t = bid - 512;
    int ccol = (t & 3) * 128, crow = (t >> 2) * 128;
    gemm_tile(a3k, w3, kk, 512, INV_SCALE, nullptr, crow, ccol, smdyn);
  } else {
    int t = bid - 640;
    int ccol = (t & 3) * 128, crow = (t >> 2) * 128;
    gemm_tile(a3v, w3 + (size_t)512 * SKP, vv, 512, 1.0f, nullptr, crow, ccol, smdyn);
  }
}

// output projection GEMM
__global__ __launch_bounds__(256, 2) void gemm_wd(
    const __nv_bfloat16* __restrict__ a3, const __nv_bfloat16* __restrict__ w3,
    float* __restrict__ out) {
  extern __shared__ __align__(128) char smdyn[];
  gemm_tile(a3, w3 + (size_t)3072 * SKP, out, 2048, 1.0f, nullptr,
            blockIdx.y * 128, blockIdx.x * 128, smdyn);
}

// ================= scan pass A: composed chunk maps =================
__global__ void amat_kernel() {
  int c = blockIdx.x;
  int b = threadIdx.x;
  float s[NSLOTS];
#pragma unroll
  for (int j = 0; j < NSLOTS; j++) s[j] = (j == b) ? 1.f : 0.f;
  int t0 = c * CLEN;
  for (int t = t0; t < t0 + CLEN; t++) {
    gate_step(s, key_div4(t));
    s[0] = 0.f;
  }
#pragma unroll
  for (int j = 0; j < NSLOTS; j++) d_amat[(c * NSLOTS + j) * NSLOTS + b] = s[j];
}

// ================= scan pass 1: local scans =================
__global__ __launch_bounds__(128) void scan_pass1() {
  int c = blockIdx.x;
  int g = blockIdx.y * 128 + threadIdx.x;
  const float* src = (g < 512) ? (d_kk + g) : (d_vv + (g - 512));
  float s[NSLOTS];
#pragma unroll
  for (int j = 0; j < NSLOTS; j++) s[j] = 0.f;
  int t0 = c * CLEN;
  for (int t = t0; t < t0 + CLEN; t++) {
    gate_step(s, key_div4(t));
    s[0] = src[(size_t)t * 512];
  }
#pragma unroll
  for (int j = 0; j < NSLOTS; j++) d_lend[(c * NDIMS + g) * NSLOTS + j] = s[j];
}

// ================= scan pass 2: carry propagation =================
__global__ __launch_bounds__(256) void scan_pass2() {
  int g = blockIdx.x * 8 + (threadIdx.x >> 5);
  int j = threadIdx.x & 31;
  float carry = 0.f;
  for (int c = 0; c < NCHUNK; c++) {
    d_carryb[(c * NDIMS + g) * NSLOTS + j] = carry;
    float nc = d_lend[(c * NDIMS + g) * NSLOTS + j];
    const float* arow = &d_amat[(c * NSLOTS + j) * NSLOTS];
#pragma unroll
    for (int i = 0; i < NSLOTS; i++) {
      float ci = __shfl_sync(0xffffffffu, carry, i);
      nc = fmaf(arow[i], ci, nc);
    }
    carry = nc;
  }
}

// ================= fused scan + rmsnorm + attention =================
__global__ __launch_bounds__(256) void scan_attn_kernel(
    const float* __restrict__ key_pos, const float* __restrict__ ln_k_w,
    const float* __restrict__ ln_v_w, __nv_bfloat16* __restrict__ out) {
  __shared__ float ksh[NSLOTS][KPITCH];
  __shared__ float vsh[NSLOTS][KPITCH];
  __shared__ float qsh[4 * 128];
  __shared__ float vsc[NSLOTS];
  __shared__ float psh[4][NSLOTS];
  __shared__ float lnv[128];

  const int c = blockIdx.x;
  const int kv = blockIdx.y;
  const int tid = threadIdx.x;
  const int d = tid & 127;
  const bool isV = tid >= 128;
  const int warp = tid >> 5;
  const int lane = tid & 31;

  if (isV) lnv[d] = ln_v_w[d];

  const int g = isV ? (512 + kv * 128 + d) : (kv * 128 + d);
  float s[NSLOTS];
  const float* carry = &d_carryb[(c * NDIMS + g) * NSLOTS];
#pragma unroll
  for (int j = 0; j < NSLOTS; j++) s[j] = carry[j];

  float kp[NSLOTS];
  if (!isV) {
#pragma unroll
    for (int j = 0; j < NSLOTS; j++) kp[j] = key_pos[d * NSLOTS + j];
  } else {
#pragma unroll
    for (int j = 0; j < NSLOTS; j++) kp[j] = 0.f;
  }

  float* col = isV ? &vsh[0][d] : &ksh[0][d];
#pragma unroll
  for (int j = 0; j < NSLOTS; j++) col[j * KPITCH] = s[j] + kp[j];

  const float* src = isV ? &d_vv[kv * 128 + d] : &d_kk[kv * 128 + d];
  const float* qrow = &d_qq[(size_t)(c * CLEN) * 2048 + kv * 512];
  const float lnkA = ln_k_w[(tid * 2) & 127];
  const float lnkB = ln_k_w[(tid * 2 + 1) & 127];

  const int t0 = c * CLEN;
  float x_next = src[(size_t)t0 * 512];
  float2 q_next = *(const float2*)&qrow[tid * 2];

  for (int it = 0; it < CLEN; it++) {
    const int t = t0 + it;
    const int kdiv = key_div4(t);
    const float x = x_next;
    const float2 qv = q_next;
    const int itn = (it + 1 < CLEN) ? it + 1 : it;
    x_next = src[(size_t)(t0 + itn) * 512];
    q_next = *(const float2*)&qrow[(size_t)itn * 2048 + tid * 2];

    // --- phase A: recurrence step + store changed slots; stage q ---
    switch (kdiv) {
      case 1: step_store<4>(s, kp, col, x); break;
      case 2: step_store<8>(s, kp, col, x); break;
      case 3: step_store<12>(s, kp, col, x); break;
      case 4: step_store<16>(s, kp, col, x); break;
      case 5: step_store<20>(s, kp, col, x); break;
      case 6: step_store<24>(s, kp, col, x); break;
      case 7: step_store<28>(s, kp, col, x); break;
      default: step_store<32>(s, kp, col, x); break;
    }
    qsh[tid * 2] = qv.x * lnkA;
    qsh[tid * 2 + 1] = qv.y * lnkB;
    __syncthreads();

    // --- phase B: warps 0-3 fused logits + k-rms + softmax; warps 4-7 v-rms ---
    if (warp < 4) {
      const int e = lane;
      const float4* qv4 = (const float4*)&qsh[warp * 128];
      const float* kr = &ksh[e][0];
      float acc0 = 0.f, acc1 = 0.f, ss0 = 0.f, ss1 = 0.f;
#pragma unroll
      for (int i = 0; i < 32; i++) {
        float4 a = qv4[i];
        float b0 = kr[4 * i], b1 = kr[4 * i + 1], b2 = kr[4 * i + 2], b3 = kr[4 * i + 3];
        acc0 = fmaf(a.x, b0, acc0); ss0 = fmaf(b0, b0, ss0);
        acc1 = fmaf(a.y, b1, acc1); ss1 = fmaf(b1, b1, ss1);
        acc0 = fmaf(a.z, b2, acc0); ss0 = fmaf(b2, b2, ss0);
        acc1 = fmaf(a.w, b3, acc1); ss1 = fmaf(b3, b3, ss1);
      }
      float acc = acc0 + acc1;
      float ss = ss0 + ss1;
      float l = acc * rsqrtf(ss * (1.0f / 128.0f) + EPSF);
      float m = l;
#pragma unroll
      for (int off = 16; off; off >>= 1) m = fmaxf(m, __shfl_xor_sync(0xffffffffu, m, off));
      float p = __expf(l - m);
      float sum = p;
#pragma unroll
      for (int off = 16; off; off >>= 1) sum += __shfl_xor_sync(0xffffffffu, sum, off);
      psh[warp][e] = p / sum;
    } else {
      const int jm = (it == 0) ? 31 : min(kdiv * 4, 31);
      const int base = (warp - 4) * 8;
#pragma unroll
      for (int i = 0; i < 8; i++) {
        const int j = base + i;
        if (j <= jm) {
          float x0 = vsh[j][lane], x1 = vsh[j][lane + 32];
          float x2 = vsh[j][lane + 64], x3 = vsh[j][lane + 96];
          float ss = fmaf(x0, x0, fmaf(x1, x1, fmaf(x2, x2, x3 * x3)));
#pragma unroll
          for (int off = 16; off; off >>= 1) ss += __shfl_xor_sync(0xffffffffu, ss, off);
          if (lane == 0) vsc[j] = rsqrtf(ss * (1.0f / 128.0f) + EPSF);
        }
      }
    }
    __syncthreads();

    // --- phase C: AV + direct bf16 [hi|lo] store (width 4096) ---
    {
      const int hx = (tid >> 7) * 2;
      float a0 = 0.f, a1 = 0.f, a2 = 0.f, a3 = 0.f;
#pragma unroll
      for (int e = 0; e < NSLOTS; e += 2) {
        float vv0 = vsh[e][d] * vsc[e];
        float vv1 = vsh[e + 1][d] * vsc[e + 1];
        a0 = fmaf(psh[hx][e], vv0, a0);
        a1 = fmaf(psh[hx + 1][e], vv0, a1);
        a2 = fmaf(psh[hx][e + 1], vv1, a2);
        a3 = fmaf(psh[hx + 1][e + 1], vv1, a3);
      }
      a0 += a2; a1 += a3;
      const float w = lnv[d];
      a0 *= w; a1 *= w;
      __nv_bfloat16* row = out + (size_t)t * SKP;
      const int c0 = kv * 512 + hx * 128 + d;
      __nv_bfloat16 h, l;
      split_bf16(a0, h, l);
      row[c0] = h; row[c0 + 2048] = l;
      split_bf16(a1, h, l);
      row[c0 + 128] = h; row[c0 + 128 + 2048] = l;
    }
    __syncthreads();
  }
}

// ================= launch =================
extern "C" void kernel_launch(void* const* d_in, const int* in_sizes, int n_in,
                              void* d_out, int out_size) {
  const float* q        = (const float*)d_in[0];
  const float* k        = (const float*)d_in[1];
  const float* v        = (const float*)d_in[2];
  const float* wq       = (const float*)d_in[3];
  const float* wk       = (const float*)d_in[4];
  const float* wv       = (const float*)d_in[5];
  const float* wd       = (const float*)d_in[6];
  const float* key_pos  = (const float*)d_in[7];
  const float* query_pos= (const float*)d_in[8];
  const float* ln_k_w   = (const float*)d_in[9];
  const float* ln_v_w   = (const float*)d_in[10];

  float *p_kk, *p_vv, *p_qq;
  __nv_bfloat16 *p_a3, *p_a3k, *p_a3v, *p_w3;
  cudaGetSymbolAddress((void**)&p_kk, d_kk);
  cudaGetSymbolAddress((void**)&p_vv, d_vv);
  cudaGetSymbolAddress((void**)&p_qq, d_qq);
  cudaGetSymbolAddress((void**)&p_a3, d_a3);
  cudaGetSymbolAddress((void**)&p_a3k, d_a3k);
  cudaGetSymbolAddress((void**)&p_a3v, d_a3v);
  cudaGetSymbolAddress((void**)&p_w3, d_w3);

  cudaFuncSetAttribute(gemm_qkv, cudaFuncAttributeMaxDynamicSharedMemorySize, GSMEM);
  cudaFuncSetAttribute(gemm_wd, cudaFuncAttributeMaxDynamicSharedMemorySize, GSMEM);

  // 1: all weight splits
  split_wt_all<<<dim3(64, 64, 4), 256>>>(wk, wv, wq, wd, p_w3);
  // 2: all activation splits
  split_act_all<<<dim3(LSEQ * EMB / 4 / 256, 1, 3), 256>>>(q, k, v, p_a3, p_a3k, p_a3v);
  // 3: composed chunk gate maps
  amat_kernel<<<NCHUNK, 32>>>();
  // 4 (PROFILED): merged q+k+v projection GEMM
  gemm_qkv<<<768, 256, GSMEM>>>(p_a3, p_a3k, p_a3v, p_w3, p_qq, p_kk, p_vv, query_pos);
  // 5-6: scan carry setup
  scan_pass1<<<dim3(NCHUNK, 8), 128>>>();
  scan_pass2<<<128, 256>>>();
  // 7: fused re-scan + rmsnorm + attention
  scan_attn_kernel<<<dim3(NCHUNK, KVHEADS), 256>>>(key_pos, ln_k_w, ln_v_w, p_a3);
  // 8: output projection
  gemm_wd<<<dim3(2048 / 128, LSEQ / 128), 256, GSMEM>>>(p_a3, p_w3, (float*)d_out);
}

// round 16
// speedup vs baseline: 1.7544x; 1.0667x over previous
#include <cuda_runtime.h>
#include <cuda_bf16.h>
#include <cstdint>
#include <math.h>

// ================= problem constants =================
#define LSEQ 4096
#define EMB 2048
#define KVHEADS 4
#define NSLOTS 32
#define NDIMS 1024
#define NCHUNK 128
#define CLEN 32                          // LSEQ / NCHUNK
#define RHALF 0.70710678118654752f
#define INV_SCALE 0.29730177875068026f   // 1 / 128^0.25
#define EPSF 1e-6f
#define SKP 4096                         // stored K' width: [hi|lo] (dedup)
#define KPITCH 133                       // bank step 5 (coprime 32): conflict-free cols

// ================= device scratch =================
__device__ float d_kk[LSEQ * 512];
__device__ float d_vv[LSEQ * 512];
__device__ float d_qq[LSEQ * 2048];
__device__ float d_lend[NCHUNK * NDIMS * NSLOTS];
__device__ float d_carryb[NCHUNK * NDIMS * NSLOTS];
__device__ float d_amat[NCHUNK * NSLOTS * NSLOTS];
__device__ __nv_bfloat16 d_a3[(size_t)LSEQ * SKP];     // q split, later attn split
__device__ __nv_bfloat16 d_a3k[(size_t)LSEQ * SKP];    // k split
__device__ __nv_bfloat16 d_a3v[(size_t)LSEQ * SKP];    // v split
__device__ __nv_bfloat16 d_w3[(size_t)5120 * SKP];
// d_w3 rows: wk@0 (512), wv@512, wq@1024 (2048), wd@3072 (2048); each row [hi|lo]

// ================= gate recurrence =================
template <int KEY>
__device__ __forceinline__ void merge_shift(float (&s)[NSLOTS]) {
  s[KEY] = RHALF * (s[KEY] + s[KEY - 1]);
#pragma unroll
  for (int j = KEY - 1; j >= 1; --j) s[j] = s[j - 1];
}

__device__ __forceinline__ void gate_step(float (&s)[NSLOTS], int kdiv) {
  switch (kdiv) {
    case 1: merge_shift<4>(s); break;
    case 2: merge_shift<8>(s); break;
    case 3: merge_shift<12>(s); break;
    case 4: merge_shift<16>(s); break;
    case 5: merge_shift<20>(s); break;
    case 6: merge_shift<24>(s); break;
    case 7: merge_shift<28>(s); break;
    default:
#pragma unroll
      for (int j = 31; j >= 1; --j) s[j] = s[j - 1];
      break;
  }
}

__device__ __forceinline__ int key_div4(int t) { return __ffs(~(t & 1023)); }

template <int KEY>
__device__ __forceinline__ void step_store(float (&s)[NSLOTS], const float (&kp)[NSLOTS],
                                           float* col, float x) {
  if (KEY < 32) {
    s[KEY] = RHALF * (s[KEY] + s[KEY - 1]);
    col[KEY * KPITCH] = s[KEY] + kp[KEY];
  }
  constexpr int TOP = (KEY < 32) ? KEY : 32;
#pragma unroll
  for (int j = TOP - 1; j >= 1; --j) {
    s[j] = s[j - 1];
    col[j * KPITCH] = s[j] + kp[j];
  }
  s[0] = x;
  col[0] = x + kp[0];
}

// ================= split helpers =================
__device__ __forceinline__ void split_bf16(float x, __nv_bfloat16& h, __nv_bfloat16& l) {
  h = __float2bfloat16_rn(x);
  l = __float2bfloat16_rn(x - __bfloat162float(h));
}

// all three activation splits in one launch: z = 0:q, 1:k, 2:v ([hi|lo], width 4096)
__global__ __launch_bounds__(256) void split_act_all(
    const float* __restrict__ q, const float* __restrict__ k,
    const float* __restrict__ v, __nv_bfloat16* __restrict__ dq,
    __nv_bfloat16* __restrict__ dk, __nv_bfloat16* __restrict__ dv) {
  const int K = EMB;
  const float* src = (blockIdx.z == 0) ? q : (blockIdx.z == 1) ? k : v;
  __nv_bfloat16* dst = (blockIdx.z == 0) ? dq : (blockIdx.z == 1) ? dk : dv;
  int idx = blockIdx.x * 256 + threadIdx.x;
  float4 vv = ((const float4*)src)[idx];
  int c = (idx % (K / 4)) * 4;
  int r = idx / (K / 4);
  __nv_bfloat16 h0, l0, h1, l1, h2, l2, h3, l3;
  split_bf16(vv.x, h0, l0); split_bf16(vv.y, h1, l1);
  split_bf16(vv.z, h2, l2); split_bf16(vv.w, h3, l3);
  __nv_bfloat162 hA(h0, h1), hB(h2, h3), lA(l0, l1), lB(l2, l3);
  __nv_bfloat16* base = dst + (size_t)r * SKP + c;
  *(__nv_bfloat162*)(base) = hA;        *(__nv_bfloat162*)(base + 2) = hB;
  *(__nv_bfloat162*)(base + K) = lA;    *(__nv_bfloat162*)(base + K + 2) = lB;
}

// all four weight splits in one launch: z = 0:wk, 1:wv, 2:wq, 3:wd ([hi|lo])
__global__ __launch_bounds__(256) void split_wt_all(
    const float* __restrict__ wk, const float* __restrict__ wv,
    const float* __restrict__ wq, const float* __restrict__ wd,
    __nv_bfloat16* __restrict__ w3) {
  const int K = EMB;
  const int z = blockIdx.z;
  const int N = (z < 2) ? 512 : 2048;
  if (blockIdx.x * 32 >= N) return;
  const float* src = (z == 0) ? wk : (z == 1) ? wv : (z == 2) ? wq : wd;
  __nv_bfloat16* dst = w3 + ((z == 0) ? 0 : (z == 1) ? (size_t)512 * SKP
                            : (z == 2) ? (size_t)1024 * SKP : (size_t)3072 * SKP);
  __shared__ float tile[32][33];
  int n0 = blockIdx.x * 32, k0 = blockIdx.y * 32;
  int tx = threadIdx.x & 31, ty = threadIdx.x >> 5;
#pragma unroll
  for (int i = 0; i < 4; i++)
    tile[ty + 8 * i][tx] = src[(size_t)(k0 + ty + 8 * i) * N + n0 + tx];
  __syncthreads();
#pragma unroll
  for (int i = 0; i < 4; i++) {
    int n = n0 + ty + 8 * i;
    int kk = k0 + tx;
    float x = tile[tx][ty + 8 * i];
    __nv_bfloat16 h, l;
    split_bf16(x, h, l);
    __nv_bfloat16* base = dst + (size_t)n * SKP;
    base[kk] = h; base[K + kk] = l;
  }
}

// ================= bf16 tensor-core GEMM core =================
// Virtual K' = 6144 (96 chunks of 64). A chunks map [hi|lo|hi] -> stored [hi|lo]
// via akt = kt>=64 ? kt-64 : kt; W chunks map [hi|hi|lo] via wkt = kt<32 ? kt : kt-32.
#define BKC 64
#define GKT 96
#define SPITCH 72
#define OPBYTES (128 * SPITCH * 2)
#define STG_BYTES (2 * OPBYTES)
#define GSMEM (3 * STG_BYTES)

__device__ __forceinline__ int a_chunk(int kt) { return (kt >= 64) ? kt - 64 : kt; }
__device__ __forceinline__ int w_chunk(int kt) { return (kt < 32) ? kt : kt - 32; }

__device__ __forceinline__ void mma16816(float (&c)[4], const unsigned (&a)[4],
                                         unsigned b0, unsigned b1) {
  asm volatile(
      "mma.sync.aligned.m16n8k16.row.col.f32.bf16.bf16.f32 "
      "{%0,%1,%2,%3}, {%4,%5,%6,%7}, {%8,%9}, {%0,%1,%2,%3};"
      : "+f"(c[0]), "+f"(c[1]), "+f"(c[2]), "+f"(c[3])
      : "r"(a[0]), "r"(a[1]), "r"(a[2]), "r"(a[3]), "r"(b0), "r"(b1));
}

#define CP16(dst, src) \
  asm volatile("cp.async.cg.shared.global [%0], [%1], 16;" :: "r"(dst), "l"(src))

__device__ __forceinline__ void load_chunk(const __nv_bfloat16* gA,
                                           const __nv_bfloat16* gB, int kt,
                                           unsigned so, unsigned oA, unsigned oB) {
  const __nv_bfloat16* pa = gA + (size_t)a_chunk(kt) * BKC;
  const __nv_bfloat16* pb = gB + (size_t)w_chunk(kt) * BKC;
#pragma unroll
  for (int i = 0; i < 4; i++) {
    CP16(so + oA + i * 32 * SPITCH * 2, pa + (size_t)(i * 32) * SKP);
    CP16(so + oB + i * 32 * SPITCH * 2, pb + (size_t)(i * 32) * SKP);
  }
  asm volatile("cp.async.commit_group;");
}

// one ks sub-iteration (k16): 6 ldmatrix + 16 mma
__device__ __forceinline__ void compute_ks(
    unsigned sA, unsigned sB, int k0, int a_row, int a_kof, int b_row, int b_kof,
    float (&acc)[4][4][4]) {
  unsigned a[4][4];
#pragma unroll
  for (int i = 0; i < 4; i++) {
    unsigned addr = sA + (((a_row + i * 16) * SPITCH) + k0 + a_kof) * 2;
    asm volatile(
        "ldmatrix.sync.aligned.m8n8.x4.shared.b16 {%0,%1,%2,%3}, [%4];"
        : "=r"(a[i][0]), "=r"(a[i][1]), "=r"(a[i][2]), "=r"(a[i][3])
        : "r"(addr));
  }
  unsigned b[4][2];
#pragma unroll
  for (int jj = 0; jj < 2; jj++) {
    unsigned addr = sB + (((b_row + jj * 16) * SPITCH) + k0 + b_kof) * 2;
    asm volatile(
        "ldmatrix.sync.aligned.m8n8.x4.shared.b16 {%0,%1,%2,%3}, [%4];"
        : "=r"(b[2 * jj][0]), "=r"(b[2 * jj][1]),
          "=r"(b[2 * jj + 1][0]), "=r"(b[2 * jj + 1][1])
        : "r"(addr));
  }
#pragma unroll
  for (int i = 0; i < 4; i++)
#pragma unroll
    for (int j = 0; j < 4; j++) mma16816(acc[i][j], a[i], b[j][0], b[j][1]);
}

__device__ __forceinline__ void gemm_tile(
    const __nv_bfloat16* __restrict__ A, const __nv_bfloat16* __restrict__ Bn,
    float* __restrict__ C, int N, float alpha, const float* __restrict__ bias,
    int crow, int ccol, char* smdyn) {
  const int tid = threadIdx.x;
  const int lane = tid & 31, warp = tid >> 5;
  const int wm = (warp & 1) * 64, wn = (warp >> 1) * 32;
  const int g = lane >> 2, t = lane & 3;

  const unsigned sBase = (unsigned)__cvta_generic_to_shared(smdyn);

  const int lrow = tid >> 3;
  const int lcc = (tid & 7) * 8;
  const __nv_bfloat16* gA = A + (size_t)(crow + lrow) * SKP + lcc;
  const __nv_bfloat16* gB = Bn + (size_t)(ccol + lrow) * SKP + lcc;
  const unsigned oA = (lrow * SPITCH + lcc) * 2;
  const unsigned oB = OPBYTES + (lrow * SPITCH + lcc) * 2;

  float acc[4][4][4];
#pragma unroll
  for (int i = 0; i < 4; i++)
#pragma unroll
    for (int j = 0; j < 4; j++)
#pragma unroll
      for (int r = 0; r < 4; r++) acc[i][j][r] = 0.f;

  const int a_row = wm + (lane & 15);
  const int a_kof = (lane >> 4) << 3;
  const int b_row = wn + ((lane >> 4) << 3) + (lane & 7);
  const int b_kof = ((lane >> 3) & 1) << 3;

  load_chunk(gA, gB, 0, sBase, oA, oB);
  load_chunk(gA, gB, 1, sBase + STG_BYTES, oA, oB);

  int st = 0;
  for (int kt = 0; kt < GKT; kt++) {
    if (kt + 2 < GKT) asm volatile("cp.async.wait_group 1;");
    else              asm volatile("cp.async.wait_group 0;");
    __syncthreads();

    const unsigned sA = sBase + st * STG_BYTES;
    const unsigned sB = sA + OPBYTES;

    // ks=0 first: get tensor pipe busy before spending LSU issue on prefetch
    compute_ks(sA, sB, 0, a_row, a_kof, b_row, b_kof, acc);

    if (kt + 2 < GKT) {
      int ns = st + 2; if (ns >= 3) ns -= 3;
      load_chunk(gA, gB, kt + 2, sBase + ns * STG_BYTES, oA, oB);
    }

#pragma unroll
    for (int ks = 1; ks < 4; ks++)
      compute_ks(sA, sB, ks * 16, a_row, a_kof, b_row, b_kof, acc);

    if (++st == 3) st = 0;
  }

#pragma unroll
  for (int i = 0; i < 4; i++) {
#pragma unroll
    for (int j = 0; j < 4; j++) {
      int row = crow + wm + i * 16 + g;
      int col = ccol + wn + j * 8 + 2 * t;
      float b0 = bias ? bias[col & 127] : 0.f;
      float b1 = bias ? bias[(col + 1) & 127] : 0.f;
      float2 v0 = make_float2(alpha * acc[i][j][0] + b0, alpha * acc[i][j][1] + b1);
      float2 v1 = make_float2(alpha * acc[i][j][2] + b0, alpha * acc[i][j][3] + b1);
      *(float2*)(C + (size_t)row * N + col) = v0;
      *(float2*)(C + (size_t)(row + 8) * N + col) = v1;
    }
  }
}

// merged q+k+v projection GEMM: 768 CTAs
__global__ __launch_bounds__(256, 2) void gemm_qkv(
    const __nv_bfloat16* __restrict__ a3q, const __nv_bfloat16* __restrict__ a3k,
    const __nv_bfloat16* __restrict__ a3v, const __nv_bfloat16* __restrict__ w3,
    float* __restrict__ qq, float* __restrict__ kk, float* __restrict__ vv,
    const float* __restrict__ query_pos) {
  extern __shared__ __align__(128) char smdyn[];
  const int bid = blockIdx.x;
  if (bid < 512) {
    int ccol = (bid & 15) * 128, crow = (bid >> 4) * 128;
    gemm_tile(a3q, w3 + (size_t)1024 * SKP, qq, 2048, INV_SCALE, query_pos,
              crow, ccol, smdyn);
  } else if (bid < 640) {
    int t = bid - 512;
    int ccol = (t & 3) * 128, crow = (t >> 2) * 128;
    gemm_tile(a3k, w3, kk, 512, INV_SCALE, nullptr, crow, ccol, smdyn);
  } else {
    int t = bid - 640;
    int ccol = (t & 3) * 128, crow = (t >> 2) * 128;
    gemm_tile(a3v, w3 + (size_t)512 * SKP, vv, 512, 1.0f, nullptr, crow, ccol, smdyn);
  }
}

// output projection GEMM
__global__ __launch_bounds__(256, 2) void gemm_wd(
    const __nv_bfloat16* __restrict__ a3, const __nv_bfloat16* __restrict__ w3,
    float* __restrict__ out) {
  extern __shared__ __align__(128) char smdyn[];
  gemm_tile(a3, w3 + (size_t)3072 * SKP, out, 2048, 1.0f, nullptr,
            blockIdx.y * 128, blockIdx.x * 128, smdyn);
}

// ================= scan pass A: composed chunk maps =================
__global__ void amat_kernel() {
  int c = blockIdx.x;
  int b = threadIdx.x;
  float s[NSLOTS];
#pragma unroll
  for (int j = 0; j < NSLOTS; j++) s[j] = (j == b) ? 1.f : 0.f;
  int t0 = c * CLEN;
  for (int t = t0; t < t0 + CLEN; t++) {
    gate_step(s, key_div4(t));
    s[0] = 0.f;
  }
#pragma unroll
  for (int j = 0; j < NSLOTS; j++) d_amat[(c * NSLOTS + j) * NSLOTS + b] = s[j];
}

// ================= scan pass 1: local scans =================
__global__ __launch_bounds__(128) void scan_pass1() {
  int c = blockIdx.x;
  int g = blockIdx.y * 128 + threadIdx.x;
  const float* src = (g < 512) ? (d_kk + g) : (d_vv + (g - 512));
  float s[NSLOTS];
#pragma unroll
  for (int j = 0; j < NSLOTS; j++) s[j] = 0.f;
  int t0 = c * CLEN;
  for (int t = t0; t < t0 + CLEN; t++) {
    gate_step(s, key_div4(t));
    s[0] = src[(size_t)t * 512];
  }
#pragma unroll
  for (int j = 0; j < NSLOTS; j++) d_lend[(c * NDIMS + g) * NSLOTS + j] = s[j];
}

// ================= scan pass 2: carry propagation =================
__global__ __launch_bounds__(256) void scan_pass2() {
  int g = blockIdx.x * 8 + (threadIdx.x >> 5);
  int j = threadIdx.x & 31;
  float carry = 0.f;
  for (int c = 0; c < NCHUNK; c++) {
    d_carryb[(c * NDIMS + g) * NSLOTS + j] = carry;
    float nc = d_lend[(c * NDIMS + g) * NSLOTS + j];
    const float* arow = &d_amat[(c * NSLOTS + j) * NSLOTS];
#pragma unroll
    for (int i = 0; i < NSLOTS; i++) {
      float ci = __shfl_sync(0xffffffffu, carry, i);
      nc = fmaf(arow[i], ci, nc);
    }
    carry = nc;
  }
}

// ================= fused scan + rmsnorm + attention =================
__global__ __launch_bounds__(256) void scan_attn_kernel(
    const float* __restrict__ key_pos, const float* __restrict__ ln_k_w,
    const float* __restrict__ ln_v_w, __nv_bfloat16* __restrict__ out) {
  __shared__ float ksh[NSLOTS][KPITCH];
  __shared__ float vsh[NSLOTS][KPITCH];
  __shared__ float qsh[4 * 128];
  __shared__ float vsc[NSLOTS];
  __shared__ float psh[4][NSLOTS];
  __shared__ float lnv[128];

  const int c = blockIdx.x;
  const int kv = blockIdx.y;
  const int tid = threadIdx.x;
  const int d = tid & 127;
  const bool isV = tid >= 128;
  const int warp = tid >> 5;
  const int lane = tid & 31;

  if (isV) lnv[d] = ln_v_w[d];

  const int g = isV ? (512 + kv * 128 + d) : (kv * 128 + d);
  float s[NSLOTS];
  const float* carry = &d_carryb[(c * NDIMS + g) * NSLOTS];
#pragma unroll
  for (int j = 0; j < NSLOTS; j++) s[j] = carry[j];

  float kp[NSLOTS];
  if (!isV) {
#pragma unroll
    for (int j = 0; j < NSLOTS; j++) kp[j] = key_pos[d * NSLOTS + j];
  } else {
#pragma unroll
    for (int j = 0; j < NSLOTS; j++) kp[j] = 0.f;
  }

  float* col = isV ? &vsh[0][d] : &ksh[0][d];
#pragma unroll
  for (int j = 0; j < NSLOTS; j++) col[j * KPITCH] = s[j] + kp[j];

  const float* src = isV ? &d_vv[kv * 128 + d] : &d_kk[kv * 128 + d];
  const float* qrow = &d_qq[(size_t)(c * CLEN) * 2048 + kv * 512];
  const float lnkA = ln_k_w[(tid * 2) & 127];
  const float lnkB = ln_k_w[(tid * 2 + 1) & 127];

  const int t0 = c * CLEN;
  float x_next = src[(size_t)t0 * 512];
  float2 q_next = *(const float2*)&qrow[tid * 2];

  for (int it = 0; it < CLEN; it++) {
    const int t = t0 + it;
    const int kdiv = key_div4(t);
    const float x = x_next;
    const float2 qv = q_next;
    const int itn = (it + 1 < CLEN) ? it + 1 : it;
    x_next = src[(size_t)(t0 + itn) * 512];
    q_next = *(const float2*)&qrow[(size_t)itn * 2048 + tid * 2];

    // --- phase A: recurrence step + store changed slots; stage q ---
    switch (kdiv) {
      case 1: step_store<4>(s, kp, col, x); break;
      case 2: step_store<8>(s, kp, col, x); break;
      case 3: step_store<12>(s, kp, col, x); break;
      case 4: step_store<16>(s, kp, col, x); break;
      case 5: step_store<20>(s, kp, col, x); break;
      case 6: step_store<24>(s, kp, col, x); break;
      case 7: step_store<28>(s, kp, col, x); break;
      default: step_store<32>(s, kp, col, x); break;
    }
    qsh[tid * 2] = qv.x * lnkA;
    qsh[tid * 2 + 1] = qv.y * lnkB;
    __syncthreads();

    // --- phase B: warps 0-3 fused logits + k-rms + softmax; warps 4-7 v-rms ---
    if (warp < 4) {
      const int e = lane;
      const float4* qv4 = (const float4*)&qsh[warp * 128];
      const float* kr = &ksh[e][0];
      float acc0 = 0.f, acc1 = 0.f, ss0 = 0.f, ss1 = 0.f;
#pragma unroll
      for (int i = 0; i < 32; i++) {
        float4 a = qv4[i];
        float b0 = kr[4 * i], b1 = kr[4 * i + 1], b2 = kr[4 * i + 2], b3 = kr[4 * i + 3];
        acc0 = fmaf(a.x, b0, acc0); ss0 = fmaf(b0, b0, ss0);
        acc1 = fmaf(a.y, b1, acc1); ss1 = fmaf(b1, b1, ss1);
        acc0 = fmaf(a.z, b2, acc0); ss0 = fmaf(b2, b2, ss0);
        acc1 = fmaf(a.w, b3, acc1); ss1 = fmaf(b3, b3, ss1);
      }
      float acc = acc0 + acc1;
      float ss = ss0 + ss1;
      float l = acc * rsqrtf(ss * (1.0f / 128.0f) + EPSF);
      // logits |l| << 88: exp is safe without max subtraction (saves shfl tree)
      float p = __expf(l);
      float sum = p;
#pragma unroll
      for (int off = 16; off; off >>= 1) sum += __shfl_xor_sync(0xffffffffu, sum, off);
      psh[warp][e] = p / sum;
    } else {
      const int jm = (it == 0) ? 31 : min(kdiv * 4, 31);
      const int base = (warp - 4) * 8;
#pragma unroll
      for (int i = 0; i < 8; i++) {
        const int j = base + i;
        if (j <= jm) {
          float x0 = vsh[j][lane], x1 = vsh[j][lane + 32];
          float x2 = vsh[j][lane + 64], x3 = vsh[j][lane + 96];
          float ss = fmaf(x0, x0, fmaf(x1, x1, fmaf(x2, x2, x3 * x3)));
#pragma unroll
          for (int off = 16; off; off >>= 1) ss += __shfl_xor_sync(0xffffffffu, ss, off);
          if (lane == 0) vsc[j] = rsqrtf(ss * (1.0f / 128.0f) + EPSF);
        }
      }
    }
    __syncthreads();

    // --- phase C: AV + direct bf16 [hi|lo] store (width 4096) ---
    {
      const int hx = (tid >> 7) * 2;
      float a0 = 0.f, a1 = 0.f, a2 = 0.f, a3 = 0.f;
#pragma unroll
      for (int e = 0; e < NSLOTS; e += 2) {
        float vv0 = vsh[e][d] * vsc[e];
        float vv1 = vsh[e + 1][d] * vsc[e + 1];
        a0 = fmaf(psh[hx][e], vv0, a0);
        a1 = fmaf(psh[hx + 1][e], vv0, a1);
        a2 = fmaf(psh[hx][e + 1], vv1, a2);
        a3 = fmaf(psh[hx + 1][e + 1], vv1, a3);
      }
      a0 += a2; a1 += a3;
      const float w = lnv[d];
      a0 *= w; a1 *= w;
      __nv_bfloat16* row = out + (size_t)t * SKP;
      const int c0 = kv * 512 + hx * 128 + d;
      __nv_bfloat16 h, l;
      split_bf16(a0, h, l);
      row[c0] = h; row[c0 + 2048] = l;
      split_bf16(a1, h, l);
      row[c0 + 128] = h; row[c0 + 128 + 2048] = l;
    }
    __syncthreads();
  }
}

// ================= launch =================
extern "C" void kernel_launch(void* const* d_in, const int* in_sizes, int n_in,
                              void* d_out, int out_size) {
  const float* q        = (const float*)d_in[0];
  const float* k        = (const float*)d_in[1];
  const float* v        = (const float*)d_in[2];
  const float* wq       = (const float*)d_in[3];
  const float* wk       = (const float*)d_in[4];
  const float* wv       = (const float*)d_in[5];
  const float* wd       = (const float*)d_in[6];
  const float* key_pos  = (const float*)d_in[7];
  const float* query_pos= (const float*)d_in[8];
  const float* ln_k_w   = (const float*)d_in[9];
  const float* ln_v_w   = (const float*)d_in[10];

  float *p_kk, *p_vv, *p_qq;
  __nv_bfloat16 *p_a3, *p_a3k, *p_a3v, *p_w3;
  cudaGetSymbolAddress((void**)&p_kk, d_kk);
  cudaGetSymbolAddress((void**)&p_vv, d_vv);
  cudaGetSymbolAddress((void**)&p_qq, d_qq);
  cudaGetSymbolAddress((void**)&p_a3, d_a3);
  cudaGetSymbolAddress((void**)&p_a3k, d_a3k);
  cudaGetSymbolAddress((void**)&p_a3v, d_a3v);
  cudaGetSymbolAddress((void**)&p_w3, d_w3);

  cudaFuncSetAttribute(gemm_qkv, cudaFuncAttributeMaxDynamicSharedMemorySize, GSMEM);
  cudaFuncSetAttribute(gemm_wd, cudaFuncAttributeMaxDynamicSharedMemorySize, GSMEM);

  // 1: all weight splits
  split_wt_all<<<dim3(64, 64, 4), 256>>>(wk, wv, wq, wd, p_w3);
  // 2: all activation splits
  split_act_all<<<dim3(LSEQ * EMB / 4 / 256, 1, 3), 256>>>(q, k, v, p_a3, p_a3k, p_a3v);
  // 3: composed chunk gate maps
  amat_kernel<<<NCHUNK, 32>>>();
  // 4 (PROFILED): merged q+k+v projection GEMM
  gemm_qkv<<<768, 256, GSMEM>>>(p_a3, p_a3k, p_a3v, p_w3, p_qq, p_kk, p_vv, query_pos);
  // 5-6: scan carry setup
  scan_pass1<<<dim3(NCHUNK, 8), 128>>>();
  scan_pass2<<<128, 256>>>();
  // 7: fused re-scan + rmsnorm + attention
  scan_attn_kernel<<<dim3(NCHUNK, KVHEADS), 256>>>(key_pos, ln_k_w, ln_v_w, p_a3);
  // 8: output projection
  gemm_wd<<<dim3(2048 / 128, LSEQ / 128), 256, GSMEM>>>(p_a3, p_w3, (float*)d_out);
}

// round 17
// speedup vs baseline: 1.8033x; 1.0279x over previous
#include <cuda_runtime.h>
#include <cuda_bf16.h>
#include <cstdint>
#include <math.h>

// ================= problem constants =================
#define LSEQ 4096
#define EMB 2048
#define KVHEADS 4
#define NSLOTS 32
#define NDIMS 1024
#define NCHUNK 128
#define CLEN 32                          // LSEQ / NCHUNK
#define RHALF 0.70710678118654752f
#define INV_SCALE 0.29730177875068026f   // 1 / 128^0.25
#define EPSF 1e-6f
#define SKP 4096                         // stored K' width: [hi|lo] (dedup)
#define KPITCH 133                       // bank step 5 (coprime 32): conflict-free cols

// ================= device scratch =================
__device__ float d_kk[LSEQ * 512];
__device__ float d_vv[LSEQ * 512];
__device__ float d_qq[LSEQ * 2048];
__device__ float d_lend[NCHUNK * NDIMS * NSLOTS];
__device__ float d_carryb[NCHUNK * NDIMS * NSLOTS];
__device__ float d_amat[NCHUNK * NSLOTS * NSLOTS];
__device__ __nv_bfloat16 d_a3[(size_t)LSEQ * SKP];     // q split, later attn split
__device__ __nv_bfloat16 d_a3k[(size_t)LSEQ * SKP];    // k split
__device__ __nv_bfloat16 d_a3v[(size_t)LSEQ * SKP];    // v split
__device__ __nv_bfloat16 d_w3[(size_t)5120 * SKP];
// d_w3 rows: wk@0 (512), wv@512, wq@1024 (2048), wd@3072 (2048); each row [hi|lo]

// ================= gate recurrence =================
template <int KEY>
__device__ __forceinline__ void merge_shift(float (&s)[NSLOTS]) {
  s[KEY] = RHALF * (s[KEY] + s[KEY - 1]);
#pragma unroll
  for (int j = KEY - 1; j >= 1; --j) s[j] = s[j - 1];
}

__device__ __forceinline__ void gate_step(float (&s)[NSLOTS], int kdiv) {
  switch (kdiv) {
    case 1: merge_shift<4>(s); break;
    case 2: merge_shift<8>(s); break;
    case 3: merge_shift<12>(s); break;
    case 4: merge_shift<16>(s); break;
    case 5: merge_shift<20>(s); break;
    case 6: merge_shift<24>(s); break;
    case 7: merge_shift<28>(s); break;
    default:
#pragma unroll
      for (int j = 31; j >= 1; --j) s[j] = s[j - 1];
      break;
  }
}

__device__ __forceinline__ int key_div4(int t) { return __ffs(~(t & 1023)); }

template <int KEY>
__device__ __forceinline__ void step_store(float (&s)[NSLOTS], const float (&kp)[NSLOTS],
                                           float* col, float x) {
  if (KEY < 32) {
    s[KEY] = RHALF * (s[KEY] + s[KEY - 1]);
    col[KEY * KPITCH] = s[KEY] + kp[KEY];
  }
  constexpr int TOP = (KEY < 32) ? KEY : 32;
#pragma unroll
  for (int j = TOP - 1; j >= 1; --j) {
    s[j] = s[j - 1];
    col[j * KPITCH] = s[j] + kp[j];
  }
  s[0] = x;
  col[0] = x + kp[0];
}

// ================= split helpers =================
__device__ __forceinline__ void split_bf16(float x, __nv_bfloat16& h, __nv_bfloat16& l) {
  h = __float2bfloat16_rn(x);
  l = __float2bfloat16_rn(x - __bfloat162float(h));
}

// all three activation splits in one launch: z = 0:q, 1:k, 2:v ([hi|lo], width 4096)
__global__ __launch_bounds__(256) void split_act_all(
    const float* __restrict__ q, const float* __restrict__ k,
    const float* __restrict__ v, __nv_bfloat16* __restrict__ dq,
    __nv_bfloat16* __restrict__ dk, __nv_bfloat16* __restrict__ dv) {
  const int K = EMB;
  const float* src = (blockIdx.z == 0) ? q : (blockIdx.z == 1) ? k : v;
  __nv_bfloat16* dst = (blockIdx.z == 0) ? dq : (blockIdx.z == 1) ? dk : dv;
  int idx = blockIdx.x * 256 + threadIdx.x;
  float4 vv = ((const float4*)src)[idx];
  int c = (idx % (K / 4)) * 4;
  int r = idx / (K / 4);
  __nv_bfloat16 h0, l0, h1, l1, h2, l2, h3, l3;
  split_bf16(vv.x, h0, l0); split_bf16(vv.y, h1, l1);
  split_bf16(vv.z, h2, l2); split_bf16(vv.w, h3, l3);
  __nv_bfloat162 hA(h0, h1), hB(h2, h3), lA(l0, l1), lB(l2, l3);
  __nv_bfloat16* base = dst + (size_t)r * SKP + c;
  *(__nv_bfloat162*)(base) = hA;        *(__nv_bfloat162*)(base + 2) = hB;
  *(__nv_bfloat162*)(base + K) = lA;    *(__nv_bfloat162*)(base + K + 2) = lB;
}

// all four weight splits in one launch: z = 0:wk, 1:wv, 2:wq, 3:wd ([hi|lo])
__global__ __launch_bounds__(256) void split_wt_all(
    const float* __restrict__ wk, const float* __restrict__ wv,
    const float* __restrict__ wq, const float* __restrict__ wd,
    __nv_bfloat16* __restrict__ w3) {
  const int K = EMB;
  const int z = blockIdx.z;
  const int N = (z < 2) ? 512 : 2048;
  if (blockIdx.x * 32 >= N) return;
  const float* src = (z == 0) ? wk : (z == 1) ? wv : (z == 2) ? wq : wd;
  __nv_bfloat16* dst = w3 + ((z == 0) ? 0 : (z == 1) ? (size_t)512 * SKP
                            : (z == 2) ? (size_t)1024 * SKP : (size_t)3072 * SKP);
  __shared__ float tile[32][33];
  int n0 = blockIdx.x * 32, k0 = blockIdx.y * 32;
  int tx = threadIdx.x & 31, ty = threadIdx.x >> 5;
#pragma unroll
  for (int i = 0; i < 4; i++)
    tile[ty + 8 * i][tx] = src[(size_t)(k0 + ty + 8 * i) * N + n0 + tx];
  __syncthreads();
#pragma unroll
  for (int i = 0; i < 4; i++) {
    int n = n0 + ty + 8 * i;
    int kk = k0 + tx;
    float x = tile[tx][ty + 8 * i];
    __nv_bfloat16 h, l;
    split_bf16(x, h, l);
    __nv_bfloat16* base = dst + (size_t)n * SKP;
    base[kk] = h; base[K + kk] = l;
  }
}

// ================= bf16 tensor-core GEMM core =================
// Virtual K' = 6144 (96 chunks of 64). A chunks map [hi|lo|hi] -> stored [hi|lo]
// via akt = kt>=64 ? kt-64 : kt; W chunks map [hi|hi|lo] via wkt = kt<32 ? kt : kt-32.
#define BKC 64
#define GKT 96
#define SPITCH 72
#define OPBYTES (128 * SPITCH * 2)
#define STG_BYTES (2 * OPBYTES)
#define GSMEM (3 * STG_BYTES)

__device__ __forceinline__ int a_chunk(int kt) { return (kt >= 64) ? kt - 64 : kt; }
__device__ __forceinline__ int w_chunk(int kt) { return (kt < 32) ? kt : kt - 32; }

__device__ __forceinline__ void mma16816(float (&c)[4], const unsigned (&a)[4],
                                         unsigned b0, unsigned b1) {
  asm volatile(
      "mma.sync.aligned.m16n8k16.row.col.f32.bf16.bf16.f32 "
      "{%0,%1,%2,%3}, {%4,%5,%6,%7}, {%8,%9}, {%0,%1,%2,%3};"
      : "+f"(c[0]), "+f"(c[1]), "+f"(c[2]), "+f"(c[3])
      : "r"(a[0]), "r"(a[1]), "r"(a[2]), "r"(a[3]), "r"(b0), "r"(b1));
}

#define CP16(dst, src) \
  asm volatile("cp.async.cg.shared.global [%0], [%1], 16;" :: "r"(dst), "l"(src))

// half 0: A-tile rows; half 1: B-tile rows + commit
template <int HALF>
__device__ __forceinline__ void load_chunk_half(const __nv_bfloat16* gA,
                                                const __nv_bfloat16* gB, int kt,
                                                unsigned so, unsigned oA, unsigned oB) {
  if (HALF == 0) {
    const __nv_bfloat16* pa = gA + (size_t)a_chunk(kt) * BKC;
#pragma unroll
    for (int i = 0; i < 4; i++)
      CP16(so + oA + i * 32 * SPITCH * 2, pa + (size_t)(i * 32) * SKP);
  } else {
    const __nv_bfloat16* pb = gB + (size_t)w_chunk(kt) * BKC;
#pragma unroll
    for (int i = 0; i < 4; i++)
      CP16(so + oB + i * 32 * SPITCH * 2, pb + (size_t)(i * 32) * SKP);
    asm volatile("cp.async.commit_group;");
  }
}

// one ks sub-iteration (k16): 6 ldmatrix + 16 mma
__device__ __forceinline__ void compute_ks(
    unsigned sA, unsigned sB, int k0, int a_row, int a_kof, int b_row, int b_kof,
    float (&acc)[4][4][4]) {
  unsigned a[4][4];
#pragma unroll
  for (int i = 0; i < 4; i++) {
    unsigned addr = sA + (((a_row + i * 16) * SPITCH) + k0 + a_kof) * 2;
    asm volatile(
        "ldmatrix.sync.aligned.m8n8.x4.shared.b16 {%0,%1,%2,%3}, [%4];"
        : "=r"(a[i][0]), "=r"(a[i][1]), "=r"(a[i][2]), "=r"(a[i][3])
        : "r"(addr));
  }
  unsigned b[4][2];
#pragma unroll
  for (int jj = 0; jj < 2; jj++) {
    unsigned addr = sB + (((b_row + jj * 16) * SPITCH) + k0 + b_kof) * 2;
    asm volatile(
        "ldmatrix.sync.aligned.m8n8.x4.shared.b16 {%0,%1,%2,%3}, [%4];"
        : "=r"(b[2 * jj][0]), "=r"(b[2 * jj][1]),
          "=r"(b[2 * jj + 1][0]), "=r"(b[2 * jj + 1][1])
        : "r"(addr));
  }
#pragma unroll
  for (int i = 0; i < 4; i++)
#pragma unroll
    for (int j = 0; j < 4; j++) mma16816(acc[i][j], a[i], b[j][0], b[j][1]);
}

__device__ __forceinline__ void gemm_tile(
    const __nv_bfloat16* __restrict__ A, const __nv_bfloat16* __restrict__ Bn,
    float* __restrict__ C, int N, float alpha, const float* __restrict__ bias,
    int crow, int ccol, char* smdyn) {
  const int tid = threadIdx.x;
  const int lane = tid & 31, warp = tid >> 5;
  const int wm = (warp & 1) * 64, wn = (warp >> 1) * 32;
  const int g = lane >> 2, t = lane & 3;

  const unsigned sBase = (unsigned)__cvta_generic_to_shared(smdyn);

  const int lrow = tid >> 3;
  const int lcc = (tid & 7) * 8;
  const __nv_bfloat16* gA = A + (size_t)(crow + lrow) * SKP + lcc;
  const __nv_bfloat16* gB = Bn + (size_t)(ccol + lrow) * SKP + lcc;
  const unsigned oA = (lrow * SPITCH + lcc) * 2;
  const unsigned oB = OPBYTES + (lrow * SPITCH + lcc) * 2;

  float acc[4][4][4];
#pragma unroll
  for (int i = 0; i < 4; i++)
#pragma unroll
    for (int j = 0; j < 4; j++)
#pragma unroll
      for (int r = 0; r < 4; r++) acc[i][j][r] = 0.f;

  const int a_row = wm + (lane & 15);
  const int a_kof = (lane >> 4) << 3;
  const int b_row = wn + ((lane >> 4) << 3) + (lane & 7);
  const int b_kof = ((lane >> 3) & 1) << 3;

  load_chunk_half<0>(gA, gB, 0, sBase, oA, oB);
  load_chunk_half<1>(gA, gB, 0, sBase, oA, oB);
  load_chunk_half<0>(gA, gB, 1, sBase + STG_BYTES, oA, oB);
  load_chunk_half<1>(gA, gB, 1, sBase + STG_BYTES, oA, oB);

  int st = 0;
  for (int kt = 0; kt < GKT; kt++) {
    if (kt + 2 < GKT) asm volatile("cp.async.wait_group 1;");
    else              asm volatile("cp.async.wait_group 0;");
    __syncthreads();

    const unsigned sA = sBase + st * STG_BYTES;
    const unsigned sB = sA + OPBYTES;

    int ns = st + 2; if (ns >= 3) ns -= 3;
    const unsigned so = sBase + ns * STG_BYTES;
    const bool pf = (kt + 2 < GKT);

    // interleave prefetch halves between compute sub-iterations
    compute_ks(sA, sB, 0, a_row, a_kof, b_row, b_kof, acc);
    if (pf) load_chunk_half<0>(gA, gB, kt + 2, so, oA, oB);
    compute_ks(sA, sB, 16, a_row, a_kof, b_row, b_kof, acc);
    if (pf) load_chunk_half<1>(gA, gB, kt + 2, so, oA, oB);
    compute_ks(sA, sB, 32, a_row, a_kof, b_row, b_kof, acc);
    compute_ks(sA, sB, 48, a_row, a_kof, b_row, b_kof, acc);

    if (++st == 3) st = 0;
  }

#pragma unroll
  for (int i = 0; i < 4; i++) {
#pragma unroll
    for (int j = 0; j < 4; j++) {
      int row = crow + wm + i * 16 + g;
      int col = ccol + wn + j * 8 + 2 * t;
      float b0 = bias ? bias[col & 127] : 0.f;
      float b1 = bias ? bias[(col + 1) & 127] : 0.f;
      float2 v0 = make_float2(alpha * acc[i][j][0] + b0, alpha * acc[i][j][1] + b1);
      float2 v1 = make_float2(alpha * acc[i][j][2] + b0, alpha * acc[i][j][3] + b1);
      *(float2*)(C + (size_t)row * N + col) = v0;
      *(float2*)(C + (size_t)(row + 8) * N + col) = v1;
    }
  }
}

// merged q+k+v projection GEMM: 768 CTAs
__global__ __launch_bounds__(256, 2) void gemm_qkv(
    const __nv_bfloat16* __restrict__ a3q, const __nv_bfloat16* __restrict__ a3k,
    const __nv_bfloat16* __restrict__ a3v, const __nv_bfloat16* __restrict__ w3,
    float* __restrict__ qq, float* __restrict__ kk, float* __restrict__ vv,
    const float* __restrict__ query_pos) {
  extern __shared__ __align__(128) char smdyn[];
  const int bid = blockIdx.x;
  if (bid < 512) {
    int ccol = (bid & 15) * 128, crow = (bid >> 4) * 128;
    gemm_tile(a3q, w3 + (size_t)1024 * SKP, qq, 2048, INV_SCALE, query_pos,
              crow, ccol, smdyn);
  } else if (bid < 640) {
    int t = bid - 512;
    int ccol = (t & 3) * 128, crow = (t >> 2) * 128;
    gemm_tile(a3k, w3, kk, 512, INV_SCALE, nullptr, crow, ccol, smdyn);
  } else {
    int t = bid - 640;
    int ccol = (t & 3) * 128, crow = (t >> 2) * 128;
    gemm_tile(a3v, w3 + (size_t)512 * SKP, vv, 512, 1.0f, nullptr, crow, ccol, smdyn);
  }
}

// output projection GEMM
__global__ __launch_bounds__(256, 2) void gemm_wd(
    const __nv_bfloat16* __restrict__ a3, const __nv_bfloat16* __restrict__ w3,
    float* __restrict__ out) {
  extern __shared__ __align__(128) char smdyn[];
  gemm_tile(a3, w3 + (size_t)3072 * SKP, out, 2048, 1.0f, nullptr,
            blockIdx.y * 128, blockIdx.x * 128, smdyn);
}

// ================= scan pass A: composed chunk maps =================
__global__ void amat_kernel() {
  int c = blockIdx.x;
  int b = threadIdx.x;
  float s[NSLOTS];
#pragma unroll
  for (int j = 0; j < NSLOTS; j++) s[j] = (j == b) ? 1.f : 0.f;
  int t0 = c * CLEN;
  for (int t = t0; t < t0 + CLEN; t++) {
    gate_step(s, key_div4(t));
    s[0] = 0.f;
  }
#pragma unroll
  for (int j = 0; j < NSLOTS; j++) d_amat[(c * NSLOTS + j) * NSLOTS + b] = s[j];
}

// ================= scan pass 1: local scans =================
__global__ __launch_bounds__(128) void scan_pass1() {
  int c = blockIdx.x;
  int g = blockIdx.y * 128 + threadIdx.x;
  const float* src = (g < 512) ? (d_kk + g) : (d_vv + (g - 512));
  float s[NSLOTS];
#pragma unroll
  for (int j = 0; j < NSLOTS; j++) s[j] = 0.f;
  int t0 = c * CLEN;
  for (int t = t0; t < t0 + CLEN; t++) {
    gate_step(s, key_div4(t));
    s[0] = src[(size_t)t * 512];
  }
#pragma unroll
  for (int j = 0; j < NSLOTS; j++) d_lend[(c * NDIMS + g) * NSLOTS + j] = s[j];
}

// ================= scan pass 2: carry propagation =================
__global__ __launch_bounds__(256) void scan_pass2() {
  int g = blockIdx.x * 8 + (threadIdx.x >> 5);
  int j = threadIdx.x & 31;
  float carry = 0.f;
  for (int c = 0; c < NCHUNK; c++) {
    d_carryb[(c * NDIMS + g) * NSLOTS + j] = carry;
    float nc = d_lend[(c * NDIMS + g) * NSLOTS + j];
    const float* arow = &d_amat[(c * NSLOTS + j) * NSLOTS];
#pragma unroll
    for (int i = 0; i < NSLOTS; i++) {
      float ci = __shfl_sync(0xffffffffu, carry, i);
      nc = fmaf(arow[i], ci, nc);
    }
    carry = nc;
  }
}

// ================= fused scan + rmsnorm + attention =================
__global__ __launch_bounds__(256) void scan_attn_kernel(
    const float* __restrict__ key_pos, const float* __restrict__ ln_k_w,
    const float* __restrict__ ln_v_w, __nv_bfloat16* __restrict__ out) {
  __shared__ float ksh[NSLOTS][KPITCH];
  __shared__ float vsh[NSLOTS][KPITCH];
  __shared__ float qsh[4 * 128];
  __shared__ float vsc[NSLOTS];
  __shared__ float psh[4][NSLOTS];
  __shared__ float lnv[128];

  const int c = blockIdx.x;
  const int kv = blockIdx.y;
  const int tid = threadIdx.x;
  const int d = tid & 127;
  const bool isV = tid >= 128;
  const int warp = tid >> 5;
  const int lane = tid & 31;

  if (isV) lnv[d] = ln_v_w[d];

  const int g = isV ? (512 + kv * 128 + d) : (kv * 128 + d);
  float s[NSLOTS];
  const float* carry = &d_carryb[(c * NDIMS + g) * NSLOTS];
#pragma unroll
  for (int j = 0; j < NSLOTS; j++) s[j] = carry[j];

  float kp[NSLOTS];
  if (!isV) {
#pragma unroll
    for (int j = 0; j < NSLOTS; j++) kp[j] = key_pos[d * NSLOTS + j];
  } else {
#pragma unroll
    for (int j = 0; j < NSLOTS; j++) kp[j] = 0.f;
  }

  float* col = isV ? &vsh[0][d] : &ksh[0][d];
#pragma unroll
  for (int j = 0; j < NSLOTS; j++) col[j * KPITCH] = s[j] + kp[j];

  const float* src = isV ? &d_vv[kv * 128 + d] : &d_kk[kv * 128 + d];
  const float* qrow = &d_qq[(size_t)(c * CLEN) * 2048 + kv * 512];
  const float lnkA = ln_k_w[(tid * 2) & 127];
  const float lnkB = ln_k_w[(tid * 2 + 1) & 127];

  const int t0 = c * CLEN;
  float x_next = src[(size_t)t0 * 512];
  float2 q_next = *(const float2*)&qrow[tid * 2];

  for (int it = 0; it < CLEN; it++) {
    const int t = t0 + it;
    const int kdiv = key_div4(t);
    const float x = x_next;
    const float2 qv = q_next;
    const int itn = (it + 1 < CLEN) ? it + 1 : it;
    x_next = src[(size_t)(t0 + itn) * 512];
    q_next = *(const float2*)&qrow[(size_t)itn * 2048 + tid * 2];

    // --- phase A: recurrence step + store changed slots; stage q ---
    switch (kdiv) {
      case 1: step_store<4>(s, kp, col, x); break;
      case 2: step_store<8>(s, kp, col, x); break;
      case 3: step_store<12>(s, kp, col, x); break;
      case 4: step_store<16>(s, kp, col, x); break;
      case 5: step_store<20>(s, kp, col, x); break;
      case 6: step_store<24>(s, kp, col, x); break;
      case 7: step_store<28>(s, kp, col, x); break;
      default: step_store<32>(s, kp, col, x); break;
    }
    qsh[tid * 2] = qv.x * lnkA;
    qsh[tid * 2 + 1] = qv.y * lnkB;
    __syncthreads();

    // --- phase B: warps 0-3 fused logits + k-rms + softmax; warps 4-7 v-rms ---
    if (warp < 4) {
      const int e = lane;
      const float4* qv4 = (const float4*)&qsh[warp * 128];
      const float* kr = &ksh[e][0];
      float acc0 = 0.f, acc1 = 0.f, ss0 = 0.f, ss1 = 0.f;
#pragma unroll
      for (int i = 0; i < 32; i++) {
        float4 a = qv4[i];
        float b0 = kr[4 * i], b1 = kr[4 * i + 1], b2 = kr[4 * i + 2], b3 = kr[4 * i + 3];
        acc0 = fmaf(a.x, b0, acc0); ss0 = fmaf(b0, b0, ss0);
        acc1 = fmaf(a.y, b1, acc1); ss1 = fmaf(b1, b1, ss1);
        acc0 = fmaf(a.z, b2, acc0); ss0 = fmaf(b2, b2, ss0);
        acc1 = fmaf(a.w, b3, acc1); ss1 = fmaf(b3, b3, ss1);
      }
      float acc = acc0 + acc1;
      float ss = ss0 + ss1;
      float l = acc * rsqrtf(ss * (1.0f / 128.0f) + EPSF);
      // logits |l| << 88: exp safe without max subtraction
      float p = __expf(l);
      float sum = p;
#pragma unroll
      for (int off = 16; off; off >>= 1) sum += __shfl_xor_sync(0xffffffffu, sum, off);
      psh[warp][e] = __fdividef(p, sum);
    } else {
      const int jm = (it == 0) ? 31 : min(kdiv * 4, 31);
      const int base = (warp - 4) * 8;
#pragma unroll
      for (int i = 0; i < 8; i++) {
        const int j = base + i;
        if (j <= jm) {
          float x0 = vsh[j][lane], x1 = vsh[j][lane + 32];
          float x2 = vsh[j][lane + 64], x3 = vsh[j][lane + 96];
          float ss = fmaf(x0, x0, fmaf(x1, x1, fmaf(x2, x2, x3 * x3)));
#pragma unroll
          for (int off = 16; off; off >>= 1) ss += __shfl_xor_sync(0xffffffffu, ss, off);
          if (lane == 0) vsc[j] = rsqrtf(ss * (1.0f / 128.0f) + EPSF);
        }
      }
    }
    __syncthreads();

    // --- phase C: AV + direct bf16 [hi|lo] store (width 4096) ---
    {
      const int hx = (tid >> 7) * 2;
      float a0 = 0.f, a1 = 0.f, a2 = 0.f, a3 = 0.f;
#pragma unroll
      for (int e = 0; e < NSLOTS; e += 2) {
        float vv0 = vsh[e][d] * vsc[e];
        float vv1 = vsh[e + 1][d] * vsc[e + 1];
        a0 = fmaf(psh[hx][e], vv0, a0);
        a1 = fmaf(psh[hx + 1][e], vv0, a1);
        a2 = fmaf(psh[hx][e + 1], vv1, a2);
        a3 = fmaf(psh[hx + 1][e + 1], vv1, a3);
      }
      a0 += a2; a1 += a3;
      const float w = lnv[d];
      a0 *= w; a1 *= w;
      __nv_bfloat16* row = out + (size_t)t * SKP;
      const int c0 = kv * 512 + hx * 128 + d;
      __nv_bfloat16 h, l;
      split_bf16(a0, h, l);
      row[c0] = h; row[c0 + 2048] = l;
      split_bf16(a1, h, l);
      row[c0 + 128] = h; row[c0 + 128 + 2048] = l;
    }
    __syncthreads();
  }
}

// ================= launch =================
extern "C" void kernel_launch(void* const* d_in, const int* in_sizes, int n_in,
                              void* d_out, int out_size) {
  const float* q        = (const float*)d_in[0];
  const float* k        = (const float*)d_in[1];
  const float* v        = (const float*)d_in[2];
  const float* wq       = (const float*)d_in[3];
  const float* wk       = (const float*)d_in[4];
  const float* wv       = (const float*)d_in[5];
  const float* wd       = (const float*)d_in[6];
  const float* key_pos  = (const float*)d_in[7];
  const float* query_pos= (const float*)d_in[8];
  const float* ln_k_w   = (const float*)d_in[9];
  const float* ln_v_w   = (const float*)d_in[10];

  float *p_kk, *p_vv, *p_qq;
  __nv_bfloat16 *p_a3, *p_a3k, *p_a3v, *p_w3;
  cudaGetSymbolAddress((void**)&p_kk, d_kk);
  cudaGetSymbolAddress((void**)&p_vv, d_vv);
  cudaGetSymbolAddress((void**)&p_qq, d_qq);
  cudaGetSymbolAddress((void**)&p_a3, d_a3);
  cudaGetSymbolAddress((void**)&p_a3k, d_a3k);
  cudaGetSymbolAddress((void**)&p_a3v, d_a3v);
  cudaGetSymbolAddress((void**)&p_w3, d_w3);

  cudaFuncSetAttribute(gemm_qkv, cudaFuncAttributeMaxDynamicSharedMemorySize, GSMEM);
  cudaFuncSetAttribute(gemm_wd, cudaFuncAttributeMaxDynamicSharedMemorySize, GSMEM);

  // 1: all weight splits
  split_wt_all<<<dim3(64, 64, 4), 256>>>(wk, wv, wq, wd, p_w3);
  // 2: all activation splits
  split_act_all<<<dim3(LSEQ * EMB / 4 / 256, 1, 3), 256>>>(q, k, v, p_a3, p_a3k, p_a3v);
  // 3: composed chunk gate maps
  amat_kernel<<<NCHUNK, 32>>>();
  // 4 (PROFILED): merged q+k+v projection GEMM
  gemm_qkv<<<768, 256, GSMEM>>>(p_a3, p_a3k, p_a3v, p_w3, p_qq, p_kk, p_vv, query_pos);
  // 5-6: scan carry setup
  scan_pass1<<<dim3(NCHUNK, 8), 128>>>();
  scan_pass2<<<128, 256>>>();
  // 7: fused re-scan + rmsnorm + attention
  scan_attn_kernel<<<dim3(NCHUNK, KVHEADS), 256>>>(key_pos, ln_k_w, ln_v_w, p_a3);
  // 8: output projection
  gemm_wd<<<dim3(2048 / 128, LSEQ / 128), 256, GSMEM>>>(p_a3, p_w3, (float*)d_out);
}